// round 8
// baseline (speedup 1.0000x reference)
#include <cuda_runtime.h>
#include <cuda_fp16.h>
#include <math.h>
#include <stdint.h>

// Problem constants
#define BB   2
#define LL   1024
#define DD   768
#define HH   12
#define HD   64
#define NLAY 2
#define DFFN 3072
#define VV   50257
#define EOS_ID 50256
#define ROWS (BB*LL)          // 2048

// ---------------------------------------------------------------------------
// Static scratch
// ---------------------------------------------------------------------------
__device__ float g_x[ROWS*DD];
__device__ float g_qkv[ROWS*3*DD];
__device__ float g_att[ROWS*DD];
__device__ float g_tmp[ROWS*DD];
__device__ float g_ff[ROWS*DFFN];
__device__ int   g_rel[ROWS];
__device__ int   g_seg[ROWS];

__device__ __forceinline__ uint32_t smem_u32(const void* p) {
    uint32_t a;
    asm("{ .reg .u64 t; cvta.to.shared.u64 t, %1; cvt.u32.u64 %0, t; }"
        : "=r"(a) : "l"(p));
    return a;
}

__device__ __forceinline__ uint32_t packh2(float x, float y) {
    __half2 h = __floats2half2_rn(x, y);
    return *reinterpret_cast<uint32_t*>(&h);
}

__device__ __forceinline__ void ldsm_x4(uint32_t addr, uint32_t& r0, uint32_t& r1,
                                        uint32_t& r2, uint32_t& r3) {
    asm volatile("ldmatrix.sync.aligned.m8n8.x4.shared.b16 {%0,%1,%2,%3}, [%4];"
                 : "=r"(r0), "=r"(r1), "=r"(r2), "=r"(r3) : "r"(addr));
}

#define MMA16816(d, a0,a1,a2,a3, b0,b1) \
    asm volatile( \
        "mma.sync.aligned.m16n8k16.row.col.f32.f16.f16.f32 " \
        "{%0,%1,%2,%3}, {%4,%5,%6,%7}, {%8,%9}, {%0,%1,%2,%3};\n" \
        : "+f"((d)[0]), "+f"((d)[1]), "+f"((d)[2]), "+f"((d)[3]) \
        : "r"(a0), "r"(a1), "r"(a2), "r"(a3), "r"(b0), "r"(b1))

// ---------------------------------------------------------------------------
// Meta + embedding
// ---------------------------------------------------------------------------
__global__ void meta_kernel(const int* __restrict__ ids, int* __restrict__ rel,
                            int* __restrict__ seg) {
    int b = blockIdx.x;
    if (threadIdx.x != 0) return;
    int last = 0, s = 0;
    for (int l = 0; l < LL; l++) {
        int id = ids[b*LL + l];
        if (id == EOS_ID) { last = l; s += 1; }
        rel[b*LL + l] = l - last;
        seg[b*LL + l] = s;
    }
}

__global__ void embed_kernel(const int* __restrict__ ids, const int* __restrict__ rel,
                             const float* __restrict__ tok, const float* __restrict__ pos,
                             float* __restrict__ x) {
    int row = blockIdx.x;
    int id = ids[row];
    int r  = rel[row];
    const float* t = tok + (size_t)id * DD;
    const float* p = pos + (size_t)r  * DD;
    const float sc = 27.712812921102035f;  // sqrt(768)
    for (int i = threadIdx.x; i < DD; i += blockDim.x)
        x[(size_t)row*DD + i] = t[i] * sc + p[i];
}

#define HSTR 40   // halves per smem row (32 data + 8 pad)

// ---------------------------------------------------------------------------
// Narrow GEMM (128x128 tile, 4m x 2n warps, 32x64 warp tile) — small N
// ---------------------------------------------------------------------------
template<bool GELU>
__global__ __launch_bounds__(256, 2)
void gemm_f16(const float* __restrict__ A, const float* __restrict__ B,
              const float* __restrict__ bias, float* __restrict__ C,
              int M, int N, int K) {
    __shared__ __align__(16) __half SA[2][128*HSTR];
    __shared__ __align__(16) __half SB[2][128*HSTR];

    const int bm = blockIdx.x * 128;
    const int bn = blockIdx.y * 128;
    const int tid  = threadIdx.x;
    const int warp = tid >> 5;
    const int lane = tid & 31;
    const int grp  = lane >> 2;
    const int qid  = lane & 3;

    const int wm = (warp >> 1) * 32;
    const int wn = (warp & 1) * 64;

    const int lrow  = lane & 15;
    const int lcol8 = (lane >> 4) << 3;
    uint32_t aoff[2], boff[4];
#pragma unroll
    for (int i = 0; i < 2; i++)
        aoff[i] = ((wm + i*16 + lrow) * HSTR + lcol8) * 2;
#pragma unroll
    for (int p = 0; p < 4; p++)
        boff[p] = ((wn + p*16 + lrow) * HSTR + lcol8) * 2;

    const uint32_t sa0 = smem_u32(&SA[0][0]), sa1 = smem_u32(&SA[1][0]);
    const uint32_t sb0 = smem_u32(&SB[0][0]), sb1 = smem_u32(&SB[1][0]);

    float acc[2][8][4];
#pragma unroll
    for (int i = 0; i < 2; i++)
#pragma unroll
        for (int j = 0; j < 8; j++)
#pragma unroll
            for (int c = 0; c < 4; c++) acc[i][j][c] = 0.f;

    const int ntiles = K >> 5;
    float4 rA[4], rB[4];

#pragma unroll
    for (int i = 0; i < 4; i++) {
        int idx = tid + (i << 8);
        int row = idx >> 3;
        int f4  = idx & 7;
        rA[i] = *reinterpret_cast<const float4*>(A + (size_t)(bm + row) * K + f4*4);
        int gn = bn + row;
        rB[i] = (gn < N) ? *reinterpret_cast<const float4*>(B + (size_t)gn * K + f4*4)
                         : make_float4(0.f, 0.f, 0.f, 0.f);
    }
#pragma unroll
    for (int i = 0; i < 4; i++) {
        int idx = tid + (i << 8);
        int row = idx >> 3;
        int f4  = idx & 7;
        *reinterpret_cast<uint2*>(&SA[0][row*HSTR + f4*4]) =
            make_uint2(packh2(rA[i].x, rA[i].y), packh2(rA[i].z, rA[i].w));
        *reinterpret_cast<uint2*>(&SB[0][row*HSTR + f4*4]) =
            make_uint2(packh2(rB[i].x, rB[i].y), packh2(rB[i].z, rB[i].w));
    }
    __syncthreads();

    for (int t = 0; t < ntiles; t++) {
        const int cb = t & 1;
        const bool more = (t + 1 < ntiles);

        if (more) {
            int kt = (t + 1) << 5;
#pragma unroll
            for (int i = 0; i < 4; i++) {
                int idx = tid + (i << 8);
                int row = idx >> 3;
                int f4  = idx & 7;
                rA[i] = *reinterpret_cast<const float4*>(A + (size_t)(bm + row) * K + kt + f4*4);
                int gn = bn + row;
                rB[i] = (gn < N) ? *reinterpret_cast<const float4*>(B + (size_t)gn * K + kt + f4*4)
                                 : make_float4(0.f, 0.f, 0.f, 0.f);
            }
        }

        const uint32_t sa = cb ? sa1 : sa0;
        const uint32_t sb = cb ? sb1 : sb0;
#pragma unroll
        for (int ks = 0; ks < 2; ks++) {
            const uint32_t kb = ks * 32;
            uint32_t af[2][4];
#pragma unroll
            for (int i = 0; i < 2; i++)
                ldsm_x4(sa + aoff[i] + kb, af[i][0], af[i][1], af[i][2], af[i][3]);
#pragma unroll
            for (int p = 0; p < 4; p++) {
                uint32_t bf[4];
                ldsm_x4(sb + boff[p] + kb, bf[0], bf[1], bf[2], bf[3]);
#pragma unroll
                for (int i = 0; i < 2; i++) {
                    MMA16816(acc[i][2*p],   af[i][0], af[i][1], af[i][2], af[i][3], bf[0], bf[2]);
                    MMA16816(acc[i][2*p+1], af[i][0], af[i][1], af[i][2], af[i][3], bf[1], bf[3]);
                }
            }
        }

        if (more) {
            const int nb = (t + 1) & 1;
#pragma unroll
            for (int i = 0; i < 4; i++) {
                int idx = tid + (i << 8);
                int row = idx >> 3;
                int f4  = idx & 7;
                *reinterpret_cast<uint2*>(&SA[nb][row*HSTR + f4*4]) =
                    make_uint2(packh2(rA[i].x, rA[i].y), packh2(rA[i].z, rA[i].w));
                *reinterpret_cast<uint2*>(&SB[nb][row*HSTR + f4*4]) =
                    make_uint2(packh2(rB[i].x, rB[i].y), packh2(rB[i].z, rB[i].w));
            }
        }
        __syncthreads();
    }

    const bool evenN = (N & 1) == 0;
#pragma unroll
    for (int i = 0; i < 2; i++) {
#pragma unroll
        for (int j = 0; j < 8; j++) {
#pragma unroll
            for (int pr = 0; pr < 2; pr++) {
                int row = bm + wm + i*16 + grp + pr*8;
                int col = bn + wn + j*8 + (qid << 1);
                float v0 = acc[i][j][2*pr + 0];
                float v1 = acc[i][j][2*pr + 1];
                if (bias) { v0 += bias[col]; if (col + 1 < N) v1 += bias[col + 1]; }
                if (GELU) {
                    v0 = 0.5f * v0 * (1.0f + erff(v0 * 0.7071067811865475f));
                    v1 = 0.5f * v1 * (1.0f + erff(v1 * 0.7071067811865475f));
                }
                size_t base = (size_t)row * N + col;
                if (col + 1 < N) {
                    if (evenN) *reinterpret_cast<float2*>(&C[base]) = make_float2(v0, v1);
                    else { C[base] = v0; C[base + 1] = v1; }
                } else if (col < N) {
                    C[base] = v0;
                }
            }
        }
    }
}

// ---------------------------------------------------------------------------
// Wide GEMM (128x256 tile, 2m x 4n warps, 64x64 warp tile) — large N.
// Halves smem fragment bytes per MAC vs narrow kernel.
// Dynamic smem: SA 2x128xHSTR halves, SB 2x256xHSTR halves = 61440 B.
// ---------------------------------------------------------------------------
#define WSMEM ((2*128*HSTR + 2*256*HSTR) * 2)
#define W_SA(buf) ((buf) * 128 * HSTR)
#define W_SB(buf) (2*128*HSTR + (buf) * 256 * HSTR)

template<bool GELU>
__global__ __launch_bounds__(256, 1)
void gemm_f16_wide(const float* __restrict__ A, const float* __restrict__ B,
                   const float* __restrict__ bias, float* __restrict__ C,
                   int M, int N, int K) {
    extern __shared__ __align__(16) __half WS[];

    const int bm = blockIdx.x * 128;
    const int bn = blockIdx.y * 256;
    const int tid  = threadIdx.x;
    const int warp = tid >> 5;
    const int lane = tid & 31;
    const int grp  = lane >> 2;
    const int qid  = lane & 3;

    const int wm = (warp & 1) * 64;       // 2 m-groups
    const int wn = (warp >> 1) * 64;      // 4 n-groups

    const int lrow  = lane & 15;
    const int lcol8 = (lane >> 4) << 3;
    uint32_t aoff[4], boff[4];
#pragma unroll
    for (int i = 0; i < 4; i++)
        aoff[i] = ((wm + i*16 + lrow) * HSTR + lcol8) * 2;
#pragma unroll
    for (int p = 0; p < 4; p++)
        boff[p] = ((wn + p*16 + lrow) * HSTR + lcol8) * 2;

    const uint32_t sbase = smem_u32(&WS[0]);

    float acc[4][8][4];
#pragma unroll
    for (int i = 0; i < 4; i++)
#pragma unroll
        for (int j = 0; j < 8; j++)
#pragma unroll
            for (int c = 0; c < 4; c++) acc[i][j][c] = 0.f;

    const int ntiles = K >> 5;
    float4 rA[4], rB[8];

    // prologue
#pragma unroll
    for (int i = 0; i < 4; i++) {
        int idx = tid + (i << 8);
        int row = idx >> 3;
        int f4  = idx & 7;
        rA[i] = *reinterpret_cast<const float4*>(A + (size_t)(bm + row) * K + f4*4);
    }
#pragma unroll
    for (int i = 0; i < 8; i++) {
        int idx = tid + (i << 8);
        int row = idx >> 3;
        int f4  = idx & 7;
        int gn  = bn + row;
        rB[i] = (gn < N) ? *reinterpret_cast<const float4*>(B + (size_t)gn * K + f4*4)
                         : make_float4(0.f, 0.f, 0.f, 0.f);
    }
#pragma unroll
    for (int i = 0; i < 4; i++) {
        int idx = tid + (i << 8);
        int row = idx >> 3;
        int f4  = idx & 7;
        *reinterpret_cast<uint2*>(&WS[W_SA(0) + row*HSTR + f4*4]) =
            make_uint2(packh2(rA[i].x, rA[i].y), packh2(rA[i].z, rA[i].w));
    }
#pragma unroll
    for (int i = 0; i < 8; i++) {
        int idx = tid + (i << 8);
        int row = idx >> 3;
        int f4  = idx & 7;
        *reinterpret_cast<uint2*>(&WS[W_SB(0) + row*HSTR + f4*4]) =
            make_uint2(packh2(rB[i].x, rB[i].y), packh2(rB[i].z, rB[i].w));
    }
    __syncthreads();

    for (int t = 0; t < ntiles; t++) {
        const int cb = t & 1;
        const bool more = (t + 1 < ntiles);

        if (more) {
            int kt = (t + 1) << 5;
#pragma unroll
            for (int i = 0; i < 4; i++) {
                int idx = tid + (i << 8);
                int row = idx >> 3;
                int f4  = idx & 7;
                rA[i] = *reinterpret_cast<const float4*>(A + (size_t)(bm + row) * K + kt + f4*4);
            }
#pragma unroll
            for (int i = 0; i < 8; i++) {
                int idx = tid + (i << 8);
                int row = idx >> 3;
                int f4  = idx & 7;
                int gn  = bn + row;
                rB[i] = (gn < N) ? *reinterpret_cast<const float4*>(B + (size_t)gn * K + kt + f4*4)
                                 : make_float4(0.f, 0.f, 0.f, 0.f);
            }
        }

        const uint32_t sa = sbase + W_SA(cb) * 2;
        const uint32_t sb = sbase + W_SB(cb) * 2;
#pragma unroll
        for (int ks = 0; ks < 2; ks++) {
            const uint32_t kb = ks * 32;
            uint32_t af[4][4];
#pragma unroll
            for (int i = 0; i < 4; i++)
                ldsm_x4(sa + aoff[i] + kb, af[i][0], af[i][1], af[i][2], af[i][3]);
#pragma unroll
            for (int p = 0; p < 4; p++) {
                uint32_t bf[4];
                ldsm_x4(sb + boff[p] + kb, bf[0], bf[1], bf[2], bf[3]);
#pragma unroll
                for (int i = 0; i < 4; i++) {
                    MMA16816(acc[i][2*p],   af[i][0], af[i][1], af[i][2], af[i][3], bf[0], bf[2]);
                    MMA16816(acc[i][2*p+1], af[i][0], af[i][1], af[i][2], af[i][3], bf[1], bf[3]);
                }
            }
        }

        if (more) {
            const int nb = (t + 1) & 1;
#pragma unroll
            for (int i = 0; i < 4; i++) {
                int idx = tid + (i << 8);
                int row = idx >> 3;
                int f4  = idx & 7;
                *reinterpret_cast<uint2*>(&WS[W_SA(nb) + row*HSTR + f4*4]) =
                    make_uint2(packh2(rA[i].x, rA[i].y), packh2(rA[i].z, rA[i].w));
            }
#pragma unroll
            for (int i = 0; i < 8; i++) {
                int idx = tid + (i << 8);
                int row = idx >> 3;
                int f4  = idx & 7;
                *reinterpret_cast<uint2*>(&WS[W_SB(nb) + row*HSTR + f4*4]) =
                    make_uint2(packh2(rB[i].x, rB[i].y), packh2(rB[i].z, rB[i].w));
            }
        }
        __syncthreads();
    }

    const bool evenN = (N & 1) == 0;
#pragma unroll
    for (int i = 0; i < 4; i++) {
#pragma unroll
        for (int j = 0; j < 8; j++) {
#pragma unroll
            for (int pr = 0; pr < 2; pr++) {
                int row = bm + wm + i*16 + grp + pr*8;
                int col = bn + wn + j*8 + (qid << 1);
                float v0 = acc[i][j][2*pr + 0];
                float v1 = acc[i][j][2*pr + 1];
                if (col < N && bias) v0 += bias[col];
                if (col + 1 < N && bias) v1 += bias[col + 1];
                if (GELU) {
                    v0 = 0.5f * v0 * (1.0f + erff(v0 * 0.7071067811865475f));
                    v1 = 0.5f * v1 * (1.0f + erff(v1 * 0.7071067811865475f));
                }
                size_t base = (size_t)row * N + col;
                if (col + 1 < N) {
                    if (evenN) *reinterpret_cast<float2*>(&C[base]) = make_float2(v0, v1);
                    else { C[base] = v0; C[base + 1] = v1; }
                } else if (col < N) {
                    C[base] = v0;
                }
            }
        }
    }
}

// ---------------------------------------------------------------------------
// Tiled flash attention (unchanged)
// ---------------------------------------------------------------------------
#define APAD 68
#define ATTN_SMEM (4*64*APAD*4 + 64*4)

__global__ __launch_bounds__(256, 2)
void attn_tile_kernel(const float* __restrict__ qkv, const int* __restrict__ seg,
                      float* __restrict__ o) {
    extern __shared__ float asm_[];
    float* Qt = asm_;
    float* Kt = Qt + 64*APAD;
    float* Vs = Kt + 64*APAD;
    float* Ps = Vs + 64*APAD;
    int*  sseg = (int*)(Ps + 64*APAD);

    const int qt = blockIdx.x;
    const int h  = blockIdx.y;
    const int b  = blockIdx.z;
    const int tid = threadIdx.x;
    const int tx = tid & 15, ty = tid >> 4;
    const int q0 = qt * 64;

#pragma unroll
    for (int i = 0; i < 4; i++) {
        int idx = tid + (i << 8);
        int r = idx >> 4;
        int c = (idx & 15) << 2;
        float4 v = *reinterpret_cast<const float4*>(
            qkv + (size_t)(b*LL + q0 + r)*(3*DD) + h*HD + c);
        Qt[(c+0)*APAD + r] = v.x;
        Qt[(c+1)*APAD + r] = v.y;
        Qt[(c+2)*APAD + r] = v.z;
        Qt[(c+3)*APAD + r] = v.w;
    }
    int qseg[4];
#pragma unroll
    for (int i = 0; i < 4; i++) qseg[i] = seg[b*LL + q0 + 4*ty + i];

    float m[4], l[4], O[4][4];
#pragma unroll
    for (int i = 0; i < 4; i++) {
        m[i] = -1e30f; l[i] = 0.f;
#pragma unroll
        for (int j = 0; j < 4; j++) O[i][j] = 0.f;
    }
    __syncthreads();

    for (int kt = 0; kt <= qt; kt++) {
        const int k0 = kt * 64;
#pragma unroll
        for (int i = 0; i < 4; i++) {
            int idx = tid + (i << 8);
            int r = idx >> 4;
            int c = (idx & 15) << 2;
            const float* base = qkv + (size_t)(b*LL + k0 + r)*(3*DD) + h*HD + c;
            float4 kv = *reinterpret_cast<const float4*>(base + DD);
            Kt[(c+0)*APAD + r] = kv.x;
            Kt[(c+1)*APAD + r] = kv.y;
            Kt[(c+2)*APAD + r] = kv.z;
            Kt[(c+3)*APAD + r] = kv.w;
            float4 vv = *reinterpret_cast<const float4*>(base + 2*DD);
            *reinterpret_cast<float4*>(&Vs[r*APAD + c]) = vv;
        }
        if (tid < 64) sseg[tid] = seg[b*LL + k0 + tid];
        __syncthreads();

        float s[4][4];
#pragma unroll
        for (int i = 0; i < 4; i++)
#pragma unroll
            for (int j = 0; j < 4; j++) s[i][j] = 0.f;
#pragma unroll 8
        for (int d = 0; d < 64; d++) {
            float4 qv = *reinterpret_cast<const float4*>(&Qt[d*APAD + 4*ty]);
            float4 kv = *reinterpret_cast<const float4*>(&Kt[d*APAD + 4*tx]);
            float qa[4] = {qv.x, qv.y, qv.z, qv.w};
            float ka[4] = {kv.x, kv.y, kv.z, kv.w};
#pragma unroll
            for (int i = 0; i < 4; i++)
#pragma unroll
                for (int j = 0; j < 4; j++)
                    s[i][j] = fmaf(qa[i], ka[j], s[i][j]);
        }

#pragma unroll
        for (int i = 0; i < 4; i++) {
            int qg = q0 + 4*ty + i;
#pragma unroll
            for (int j = 0; j < 4; j++) {
                int kg = k0 + 4*tx + j;
                bool ok = (kg <= qg) && (sseg[4*tx + j] == qseg[i]);
                s[i][j] = ok ? s[i][j] * 0.125f : -1e30f;
            }
            float mt = fmaxf(fmaxf(s[i][0], s[i][1]), fmaxf(s[i][2], s[i][3]));
#pragma unroll
            for (int off = 1; off < 16; off <<= 1)
                mt = fmaxf(mt, __shfl_xor_sync(0xffffffffu, mt, off));
            float mn = fmaxf(m[i], mt);
            float fac = __expf(m[i] - mn);
            m[i] = mn;
            l[i] *= fac;
#pragma unroll
            for (int j = 0; j < 4; j++) O[i][j] *= fac;
            float rs = 0.f;
#pragma unroll
            for (int j = 0; j < 4; j++) {
                float p = __expf(s[i][j] - mn);
                s[i][j] = p;
                rs += p;
            }
#pragma unroll
            for (int off = 1; off < 16; off <<= 1)
                rs += __shfl_xor_sync(0xffffffffu, rs, off);
            l[i] += rs;
        }

#pragma unroll
        for (int i = 0; i < 4; i++)
            *reinterpret_cast<float4*>(&Ps[(4*ty + i)*APAD + 4*tx]) =
                make_float4(s[i][0], s[i][1], s[i][2], s[i][3]);
        __syncthreads();

#pragma unroll 4
        for (int k = 0; k < 64; k++) {
            float pa[4];
#pragma unroll
            for (int i = 0; i < 4; i++) pa[i] = Ps[(4*ty + i)*APAD + k];
            float4 vv = *reinterpret_cast<const float4*>(&Vs[k*APAD + 4*tx]);
            float va[4] = {vv.x, vv.y, vv.z, vv.w};
#pragma unroll
            for (int i = 0; i < 4; i++)
#pragma unroll
                for (int j = 0; j < 4; j++)
                    O[i][j] = fmaf(pa[i], va[j], O[i][j]);
        }
        __syncthreads();
    }

#pragma unroll
    for (int i = 0; i < 4; i++) {
        float inv = 1.0f / l[i];
        float4 ov = make_float4(O[i][0]*inv, O[i][1]*inv, O[i][2]*inv, O[i][3]*inv);
        *reinterpret_cast<float4*>(
            o + (size_t)(b*LL + q0 + 4*ty + i)*DD + h*HD + 4*tx) = ov;
    }
}

// ---------------------------------------------------------------------------
// Block reduction + fused add+LN
// ---------------------------------------------------------------------------
__device__ __forceinline__ float block_sum256(float v, volatile float* red) {
#pragma unroll
    for (int o = 16; o; o >>= 1) v += __shfl_xor_sync(0xffffffffu, v, o);
    if ((threadIdx.x & 31) == 0) red[threadIdx.x >> 5] = v;
    __syncthreads();
    if (threadIdx.x == 0) {
        float s = red[0];
#pragma unroll
        for (int i = 1; i < 8; i++) s += red[i];
        red[0] = s;
    }
    __syncthreads();
    float r = red[0];
    __syncthreads();
    return r;
}

__global__ __launch_bounds__(256)
void add_ln_kernel(float* __restrict__ x, const float* __restrict__ r,
                   const float* __restrict__ w, const float* __restrict__ b) {
    int row = blockIdx.x;
    int tid = threadIdx.x;
    __shared__ float buf[DD];
    __shared__ float red[8];

    float s = 0.f;
    for (int i = tid; i < DD; i += 256) {
        float v = x[(size_t)row*DD + i] + r[(size_t)row*DD + i];
        buf[i] = v;
        s += v;
    }
    __syncthreads();
    float mean = block_sum256(s, red) * (1.0f / DD);

    float vs = 0.f;
    for (int i = tid; i < DD; i += 256) {
        float d = buf[i] - mean;
        vs += d * d;
    }
    float var = block_sum256(vs, red) * (1.0f / DD);
    float inv = rsqrtf(var + 1e-5f);

    for (int i = tid; i < DD; i += 256)
        x[(size_t)row*DD + i] = (buf[i] - mean) * inv * w[i] + b[i];
}

// ---------------------------------------------------------------------------
// Host launcher
// ---------------------------------------------------------------------------
extern "C" void kernel_launch(void* const* d_in, const int* in_sizes, int n_in,
                              void* d_out, int out_size) {
    const int*   ids   = (const int*)  d_in[0];
    const float* tok   = (const float*)d_in[1];
    const float* pos   = (const float*)d_in[2];
    const float* qkv_w = (const float*)d_in[3];
    const float* qkv_b = (const float*)d_in[4];
    const float* out_w = (const float*)d_in[5];
    const float* out_b = (const float*)d_in[6];
    const float* ln1_w = (const float*)d_in[7];
    const float* ln1_b = (const float*)d_in[8];
    const float* ln2_w = (const float*)d_in[9];
    const float* ln2_b = (const float*)d_in[10];
    const float* ff1_w = (const float*)d_in[11];
    const float* ff1_b = (const float*)d_in[12];
    const float* ff2_w = (const float*)d_in[13];
    const float* ff2_b = (const float*)d_in[14];
    float* out = (float*)d_out;

    float *x, *qkv, *att, *tmp, *ff;
    int *rel, *seg;
    cudaGetSymbolAddress((void**)&x,   g_x);
    cudaGetSymbolAddress((void**)&qkv, g_qkv);
    cudaGetSymbolAddress((void**)&att, g_att);
    cudaGetSymbolAddress((void**)&tmp, g_tmp);
    cudaGetSymbolAddress((void**)&ff,  g_ff);
    cudaGetSymbolAddress((void**)&rel, g_rel);
    cudaGetSymbolAddress((void**)&seg, g_seg);

    cudaFuncSetAttribute(attn_tile_kernel,
        cudaFuncAttributeMaxDynamicSharedMemorySize, ATTN_SMEM);
    cudaFuncSetAttribute(gemm_f16_wide<false>,
        cudaFuncAttributeMaxDynamicSharedMemorySize, WSMEM);
    cudaFuncSetAttribute(gemm_f16_wide<true>,
        cudaFuncAttributeMaxDynamicSharedMemorySize, WSMEM);

    meta_kernel<<<BB, 32>>>(ids, rel, seg);
    embed_kernel<<<ROWS, 256>>>(ids, rel, tok, pos, x);

    const int MT = ROWS / 128;  // 16, fast axis

    for (int l = 0; l < NLAY; l++) {
        gemm_f16<false><<<dim3(MT, 3*DD/128), 256>>>(
            x, qkv_w + (size_t)l*3*DD*DD, qkv_b + (size_t)l*3*DD, qkv,
            ROWS, 3*DD, DD);

        attn_tile_kernel<<<dim3(LL/64, HH, BB), 256, ATTN_SMEM>>>(qkv, seg, att);

        gemm_f16<false><<<dim3(MT, DD/128), 256>>>(
            att, out_w + (size_t)l*DD*DD, out_b + (size_t)l*DD, tmp,
            ROWS, DD, DD);

        add_ln_kernel<<<ROWS, 256>>>(x, tmp, ln1_w + (size_t)l*DD, ln1_b + (size_t)l*DD);

        gemm_f16_wide<true><<<dim3(MT, DFFN/256), 256, WSMEM>>>(
            x, ff1_w + (size_t)l*DFFN*DD, ff1_b + (size_t)l*DFFN, ff,
            ROWS, DFFN, DD);

        gemm_f16<false><<<dim3(MT, DD/128), 256>>>(
            ff, ff2_w + (size_t)l*DD*DFFN, ff2_b + (size_t)l*DD, tmp,
            ROWS, DD, DFFN);

        add_ln_kernel<<<ROWS, 256>>>(x, tmp, ln2_w + (size_t)l*DD, ln2_b + (size_t)l*DD);
    }

    gemm_f16_wide<false><<<dim3(MT, (VV + 255)/256), 256, WSMEM>>>(
        x, tok, nullptr, out, ROWS, VV, DD);
}

// round 9
// speedup vs baseline: 1.1174x; 1.1174x over previous
#include <cuda_runtime.h>
#include <cuda_fp16.h>
#include <math.h>
#include <stdint.h>

// Problem constants
#define BB   2
#define LL   1024
#define DD   768
#define HH   12
#define HD   64
#define NLAY 2
#define DFFN 3072
#define VV   50257
#define EOS_ID 50256
#define ROWS (BB*LL)          // 2048

// ---------------------------------------------------------------------------
// Static scratch
// ---------------------------------------------------------------------------
__device__ float  g_x[ROWS*DD];
__device__ float  g_qkv[ROWS*3*DD];
__device__ float  g_tmp[ROWS*DD];
__device__ int    g_rel[ROWS];
__device__ int    g_seg[ROWS];
// fp16 operands
__device__ __half h_x[ROWS*DD];
__device__ __half h_att[ROWS*DD];
__device__ __half h_ff[ROWS*DFFN];
__device__ __half h_tok[VV*DD];
__device__ __half h_qkvw[NLAY*3*DD*DD];
__device__ __half h_outw[NLAY*DD*DD];
__device__ __half h_ff1w[NLAY*DFFN*DD];
__device__ __half h_ff2w[NLAY*DD*DFFN];

__device__ __forceinline__ uint32_t smem_u32(const void* p) {
    uint32_t a;
    asm("{ .reg .u64 t; cvta.to.shared.u64 t, %1; cvt.u32.u64 %0, t; }"
        : "=r"(a) : "l"(p));
    return a;
}

__device__ __forceinline__ uint32_t packh2(float x, float y) {
    __half2 h = __floats2half2_rn(x, y);
    return *reinterpret_cast<uint32_t*>(&h);
}

__device__ __forceinline__ void ldsm_x4(uint32_t addr, uint32_t& r0, uint32_t& r1,
                                        uint32_t& r2, uint32_t& r3) {
    asm volatile("ldmatrix.sync.aligned.m8n8.x4.shared.b16 {%0,%1,%2,%3}, [%4];"
                 : "=r"(r0), "=r"(r1), "=r"(r2), "=r"(r3) : "r"(addr));
}

#define MMA16816(d, a0,a1,a2,a3, b0,b1) \
    asm volatile( \
        "mma.sync.aligned.m16n8k16.row.col.f32.f16.f16.f32 " \
        "{%0,%1,%2,%3}, {%4,%5,%6,%7}, {%8,%9}, {%0,%1,%2,%3};\n" \
        : "+f"((d)[0]), "+f"((d)[1]), "+f"((d)[2]), "+f"((d)[3]) \
        : "r"(a0), "r"(a1), "r"(a2), "r"(a3), "r"(b0), "r"(b1))

// ---------------------------------------------------------------------------
// fp32 -> fp16 conversion (n % 4 == 0)
// ---------------------------------------------------------------------------
__global__ void f2h_kernel(const float* __restrict__ s, __half* __restrict__ d, int n) {
    int i = (blockIdx.x * blockDim.x + threadIdx.x) * 4;
    if (i < n) {
        float4 v = *reinterpret_cast<const float4*>(s + i);
        *reinterpret_cast<uint2*>(d + i) =
            make_uint2(packh2(v.x, v.y), packh2(v.z, v.w));
    }
}

// ---------------------------------------------------------------------------
// Meta + embedding (embed also writes fp16 copy)
// ---------------------------------------------------------------------------
__global__ void meta_kernel(const int* __restrict__ ids, int* __restrict__ rel,
                            int* __restrict__ seg) {
    int b = blockIdx.x;
    if (threadIdx.x != 0) return;
    int last = 0, s = 0;
    for (int l = 0; l < LL; l++) {
        int id = ids[b*LL + l];
        if (id == EOS_ID) { last = l; s += 1; }
        rel[b*LL + l] = l - last;
        seg[b*LL + l] = s;
    }
}

__global__ void embed_kernel(const int* __restrict__ ids, const int* __restrict__ rel,
                             const float* __restrict__ tok, const float* __restrict__ pos,
                             float* __restrict__ x, __half* __restrict__ hx) {
    int row = blockIdx.x;
    int id = ids[row];
    int r  = rel[row];
    const float* t = tok + (size_t)id * DD;
    const float* p = pos + (size_t)r  * DD;
    const float sc = 27.712812921102035f;  // sqrt(768)
    for (int i = threadIdx.x; i < DD; i += blockDim.x) {
        float v = t[i] * sc + p[i];
        x[(size_t)row*DD + i]  = v;
        hx[(size_t)row*DD + i] = __float2half(v);
    }
}

#define HSTR 40   // halves per smem row (32 data + 8 pad)

// ---------------------------------------------------------------------------
// FP16-operand GEMM: C[M,N] = A[M,K] @ B[N,K]^T (+bias)(+GELU)
// 128x128 tile, BK=32, 8 warps (4m x 2n), 32x64 warp tile, ldmatrix + m16n8k16.
// A, B are __half in gmem. OUTH selects __half output (N must be even).
// Grid: x = M-tile fast. M%128==0, K%32==0 required. N guarded.
// ---------------------------------------------------------------------------
template<bool GELU, bool OUTH>
__global__ __launch_bounds__(256, 2)
void gemm_h(const __half* __restrict__ A, const __half* __restrict__ B,
            const float* __restrict__ bias, void* __restrict__ Cv,
            int M, int N, int K) {
    __shared__ __align__(16) __half SA[2][128*HSTR];
    __shared__ __align__(16) __half SB[2][128*HSTR];

    const int bm = blockIdx.x * 128;
    const int bn = blockIdx.y * 128;
    const int tid  = threadIdx.x;
    const int warp = tid >> 5;
    const int lane = tid & 31;
    const int grp  = lane >> 2;
    const int qid  = lane & 3;

    const int wm = (warp >> 1) * 32;
    const int wn = (warp & 1) * 64;

    const int lrow  = lane & 15;
    const int lcol8 = (lane >> 4) << 3;
    uint32_t aoff[2], boff[4];
#pragma unroll
    for (int i = 0; i < 2; i++)
        aoff[i] = ((wm + i*16 + lrow) * HSTR + lcol8) * 2;
#pragma unroll
    for (int p = 0; p < 4; p++)
        boff[p] = ((wn + p*16 + lrow) * HSTR + lcol8) * 2;

    const uint32_t sa0 = smem_u32(&SA[0][0]), sa1 = smem_u32(&SA[1][0]);
    const uint32_t sb0 = smem_u32(&SB[0][0]), sb1 = smem_u32(&SB[1][0]);

    float acc[2][8][4];
#pragma unroll
    for (int i = 0; i < 2; i++)
#pragma unroll
        for (int j = 0; j < 8; j++)
#pragma unroll
            for (int c = 0; c < 4; c++) acc[i][j][c] = 0.f;

    const int ntiles = K >> 5;
    uint4 rA[2], rB[2];
    const uint4 zero4 = make_uint4(0u, 0u, 0u, 0u);

    // prologue: tile 0 -> buf 0
#pragma unroll
    for (int i = 0; i < 2; i++) {
        int idx = tid + (i << 8);           // 0..511
        int row = idx >> 2;                 // 0..127
        int s8  = (idx & 3) << 3;           // 0,8,16,24 halves
        rA[i] = *reinterpret_cast<const uint4*>(A + (size_t)(bm + row) * K + s8);
        int gn = bn + row;
        rB[i] = (gn < N) ? *reinterpret_cast<const uint4*>(B + (size_t)gn * K + s8)
                         : zero4;
    }
#pragma unroll
    for (int i = 0; i < 2; i++) {
        int idx = tid + (i << 8);
        int row = idx >> 2;
        int s8  = (idx & 3) << 3;
        *reinterpret_cast<uint4*>(&SA[0][row*HSTR + s8]) = rA[i];
        *reinterpret_cast<uint4*>(&SB[0][row*HSTR + s8]) = rB[i];
    }
    __syncthreads();

    for (int t = 0; t < ntiles; t++) {
        const int cb = t & 1;
        const bool more = (t + 1 < ntiles);

        if (more) {
            int kt = (t + 1) << 5;
#pragma unroll
            for (int i = 0; i < 2; i++) {
                int idx = tid + (i << 8);
                int row = idx >> 2;
                int s8  = (idx & 3) << 3;
                rA[i] = *reinterpret_cast<const uint4*>(A + (size_t)(bm + row) * K + kt + s8);
                int gn = bn + row;
                rB[i] = (gn < N) ? *reinterpret_cast<const uint4*>(B + (size_t)gn * K + kt + s8)
                                 : zero4;
            }
        }

        const uint32_t sa = cb ? sa1 : sa0;
        const uint32_t sb = cb ? sb1 : sb0;
#pragma unroll
        for (int ks = 0; ks < 2; ks++) {
            const uint32_t kb = ks * 32;
            uint32_t af[2][4];
#pragma unroll
            for (int i = 0; i < 2; i++)
                ldsm_x4(sa + aoff[i] + kb, af[i][0], af[i][1], af[i][2], af[i][3]);
#pragma unroll
            for (int p = 0; p < 4; p++) {
                uint32_t bf[4];
                ldsm_x4(sb + boff[p] + kb, bf[0], bf[1], bf[2], bf[3]);
#pragma unroll
                for (int i = 0; i < 2; i++) {
                    MMA16816(acc[i][2*p],   af[i][0], af[i][1], af[i][2], af[i][3], bf[0], bf[2]);
                    MMA16816(acc[i][2*p+1], af[i][0], af[i][1], af[i][2], af[i][3], bf[1], bf[3]);
                }
            }
        }

        if (more) {
            const int nb = (t + 1) & 1;
#pragma unroll
            for (int i = 0; i < 2; i++) {
                int idx = tid + (i << 8);
                int row = idx >> 2;
                int s8  = (idx & 3) << 3;
                *reinterpret_cast<uint4*>(&SA[nb][row*HSTR + s8]) = rA[i];
                *reinterpret_cast<uint4*>(&SB[nb][row*HSTR + s8]) = rB[i];
            }
        }
        __syncthreads();
    }

    // epilogue
    float*  Cf = reinterpret_cast<float*>(Cv);
    __half* Ch = reinterpret_cast<__half*>(Cv);
    const bool evenN = (N & 1) == 0;
#pragma unroll
    for (int i = 0; i < 2; i++) {
#pragma unroll
        for (int j = 0; j < 8; j++) {
#pragma unroll
            for (int pr = 0; pr < 2; pr++) {
                int row = bm + wm + i*16 + grp + pr*8;
                int col = bn + wn + j*8 + (qid << 1);
                float v0 = acc[i][j][2*pr + 0];
                float v1 = acc[i][j][2*pr + 1];
                if (bias) { v0 += bias[col]; if (col + 1 < N) v1 += bias[col + 1]; }
                if (GELU) {
                    v0 = 0.5f * v0 * (1.0f + erff(v0 * 0.7071067811865475f));
                    v1 = 0.5f * v1 * (1.0f + erff(v1 * 0.7071067811865475f));
                }
                size_t base = (size_t)row * N + col;
                if (OUTH) {
                    if (col + 1 < N) {
                        *reinterpret_cast<uint32_t*>(&Ch[base]) = packh2(v0, v1);
                    } else if (col < N) {
                        Ch[base] = __float2half(v0);
                    }
                } else {
                    if (col + 1 < N) {
                        if (evenN) *reinterpret_cast<float2*>(&Cf[base]) = make_float2(v0, v1);
                        else { Cf[base] = v0; Cf[base + 1] = v1; }
                    } else if (col < N) {
                        Cf[base] = v0;
                    }
                }
            }
        }
    }
}

// ---------------------------------------------------------------------------
// Tiled flash attention — fp32 qkv in, fp16 out (for out-proj GEMM A)
// ---------------------------------------------------------------------------
#define APAD 68
#define ATTN_SMEM (4*64*APAD*4 + 64*4)

__global__ __launch_bounds__(256, 2)
void attn_tile_kernel(const float* __restrict__ qkv, const int* __restrict__ seg,
                      __half* __restrict__ o) {
    extern __shared__ float asm_[];
    float* Qt = asm_;
    float* Kt = Qt + 64*APAD;
    float* Vs = Kt + 64*APAD;
    float* Ps = Vs + 64*APAD;
    int*  sseg = (int*)(Ps + 64*APAD);

    const int qt = blockIdx.x;
    const int h  = blockIdx.y;
    const int b  = blockIdx.z;
    const int tid = threadIdx.x;
    const int tx = tid & 15, ty = tid >> 4;
    const int q0 = qt * 64;

#pragma unroll
    for (int i = 0; i < 4; i++) {
        int idx = tid + (i << 8);
        int r = idx >> 4;
        int c = (idx & 15) << 2;
        float4 v = *reinterpret_cast<const float4*>(
            qkv + (size_t)(b*LL + q0 + r)*(3*DD) + h*HD + c);
        Qt[(c+0)*APAD + r] = v.x;
        Qt[(c+1)*APAD + r] = v.y;
        Qt[(c+2)*APAD + r] = v.z;
        Qt[(c+3)*APAD + r] = v.w;
    }
    int qseg[4];
#pragma unroll
    for (int i = 0; i < 4; i++) qseg[i] = seg[b*LL + q0 + 4*ty + i];

    float m[4], l[4], O[4][4];
#pragma unroll
    for (int i = 0; i < 4; i++) {
        m[i] = -1e30f; l[i] = 0.f;
#pragma unroll
        for (int j = 0; j < 4; j++) O[i][j] = 0.f;
    }
    __syncthreads();

    for (int kt = 0; kt <= qt; kt++) {
        const int k0 = kt * 64;
#pragma unroll
        for (int i = 0; i < 4; i++) {
            int idx = tid + (i << 8);
            int r = idx >> 4;
            int c = (idx & 15) << 2;
            const float* base = qkv + (size_t)(b*LL + k0 + r)*(3*DD) + h*HD + c;
            float4 kv = *reinterpret_cast<const float4*>(base + DD);
            Kt[(c+0)*APAD + r] = kv.x;
            Kt[(c+1)*APAD + r] = kv.y;
            Kt[(c+2)*APAD + r] = kv.z;
            Kt[(c+3)*APAD + r] = kv.w;
            float4 vv = *reinterpret_cast<const float4*>(base + 2*DD);
            *reinterpret_cast<float4*>(&Vs[r*APAD + c]) = vv;
        }
        if (tid < 64) sseg[tid] = seg[b*LL + k0 + tid];
        __syncthreads();

        float s[4][4];
#pragma unroll
        for (int i = 0; i < 4; i++)
#pragma unroll
            for (int j = 0; j < 4; j++) s[i][j] = 0.f;
#pragma unroll 8
        for (int d = 0; d < 64; d++) {
            float4 qv = *reinterpret_cast<const float4*>(&Qt[d*APAD + 4*ty]);
            float4 kv = *reinterpret_cast<const float4*>(&Kt[d*APAD + 4*tx]);
            float qa[4] = {qv.x, qv.y, qv.z, qv.w};
            float ka[4] = {kv.x, kv.y, kv.z, kv.w};
#pragma unroll
            for (int i = 0; i < 4; i++)
#pragma unroll
                for (int j = 0; j < 4; j++)
                    s[i][j] = fmaf(qa[i], ka[j], s[i][j]);
        }

#pragma unroll
        for (int i = 0; i < 4; i++) {
            int qg = q0 + 4*ty + i;
#pragma unroll
            for (int j = 0; j < 4; j++) {
                int kg = k0 + 4*tx + j;
                bool ok = (kg <= qg) && (sseg[4*tx + j] == qseg[i]);
                s[i][j] = ok ? s[i][j] * 0.125f : -1e30f;
            }
            float mt = fmaxf(fmaxf(s[i][0], s[i][1]), fmaxf(s[i][2], s[i][3]));
#pragma unroll
            for (int off = 1; off < 16; off <<= 1)
                mt = fmaxf(mt, __shfl_xor_sync(0xffffffffu, mt, off));
            float mn = fmaxf(m[i], mt);
            float fac = __expf(m[i] - mn);
            m[i] = mn;
            l[i] *= fac;
#pragma unroll
            for (int j = 0; j < 4; j++) O[i][j] *= fac;
            float rs = 0.f;
#pragma unroll
            for (int j = 0; j < 4; j++) {
                float p = __expf(s[i][j] - mn);
                s[i][j] = p;
                rs += p;
            }
#pragma unroll
            for (int off = 1; off < 16; off <<= 1)
                rs += __shfl_xor_sync(0xffffffffu, rs, off);
            l[i] += rs;
        }

#pragma unroll
        for (int i = 0; i < 4; i++)
            *reinterpret_cast<float4*>(&Ps[(4*ty + i)*APAD + 4*tx]) =
                make_float4(s[i][0], s[i][1], s[i][2], s[i][3]);
        __syncthreads();

#pragma unroll 4
        for (int k = 0; k < 64; k++) {
            float pa[4];
#pragma unroll
            for (int i = 0; i < 4; i++) pa[i] = Ps[(4*ty + i)*APAD + k];
            float4 vv = *reinterpret_cast<const float4*>(&Vs[k*APAD + 4*tx]);
            float va[4] = {vv.x, vv.y, vv.z, vv.w};
#pragma unroll
            for (int i = 0; i < 4; i++)
#pragma unroll
                for (int j = 0; j < 4; j++)
                    O[i][j] = fmaf(pa[i], va[j], O[i][j]);
        }
        __syncthreads();
    }

#pragma unroll
    for (int i = 0; i < 4; i++) {
        float inv = 1.0f / l[i];
        uint2 ov = make_uint2(packh2(O[i][0]*inv, O[i][1]*inv),
                              packh2(O[i][2]*inv, O[i][3]*inv));
        *reinterpret_cast<uint2*>(
            o + (size_t)(b*LL + q0 + 4*ty + i)*DD + h*HD + 4*tx) = ov;
    }
}

// ---------------------------------------------------------------------------
// Block reduction + fused add+LN (writes fp32 x and fp16 hx)
// ---------------------------------------------------------------------------
__device__ __forceinline__ float block_sum256(float v, volatile float* red) {
#pragma unroll
    for (int o = 16; o; o >>= 1) v += __shfl_xor_sync(0xffffffffu, v, o);
    if ((threadIdx.x & 31) == 0) red[threadIdx.x >> 5] = v;
    __syncthreads();
    if (threadIdx.x == 0) {
        float s = red[0];
#pragma unroll
        for (int i = 1; i < 8; i++) s += red[i];
        red[0] = s;
    }
    __syncthreads();
    float r = red[0];
    __syncthreads();
    return r;
}

__global__ __launch_bounds__(256)
void add_ln_kernel(float* __restrict__ x, const float* __restrict__ r,
                   const float* __restrict__ w, const float* __restrict__ b,
                   __half* __restrict__ hx) {
    int row = blockIdx.x;
    int tid = threadIdx.x;
    __shared__ float buf[DD];
    __shared__ float red[8];

    float s = 0.f;
    for (int i = tid; i < DD; i += 256) {
        float v = x[(size_t)row*DD + i] + r[(size_t)row*DD + i];
        buf[i] = v;
        s += v;
    }
    __syncthreads();
    float mean = block_sum256(s, red) * (1.0f / DD);

    float vs = 0.f;
    for (int i = tid; i < DD; i += 256) {
        float d = buf[i] - mean;
        vs += d * d;
    }
    float var = block_sum256(vs, red) * (1.0f / DD);
    float inv = rsqrtf(var + 1e-5f);

    for (int i = tid; i < DD; i += 256) {
        float v = (buf[i] - mean) * inv * w[i] + b[i];
        x[(size_t)row*DD + i]  = v;
        hx[(size_t)row*DD + i] = __float2half(v);
    }
}

// ---------------------------------------------------------------------------
// Host launcher
// ---------------------------------------------------------------------------
static inline void conv(const float* s, __half* d, long n) {
    int blocks = (int)((n/4 + 255) / 256);
    f2h_kernel<<<blocks, 256>>>(s, d, (int)n);
}

extern "C" void kernel_launch(void* const* d_in, const int* in_sizes, int n_in,
                              void* d_out, int out_size) {
    const int*   ids   = (const int*)  d_in[0];
    const float* tok   = (const float*)d_in[1];
    const float* pos   = (const float*)d_in[2];
    const float* qkv_w = (const float*)d_in[3];
    const float* qkv_b = (const float*)d_in[4];
    const float* out_w = (const float*)d_in[5];
    const float* out_b = (const float*)d_in[6];
    const float* ln1_w = (const float*)d_in[7];
    const float* ln1_b = (const float*)d_in[8];
    const float* ln2_w = (const float*)d_in[9];
    const float* ln2_b = (const float*)d_in[10];
    const float* ff1_w = (const float*)d_in[11];
    const float* ff1_b = (const float*)d_in[12];
    const float* ff2_w = (const float*)d_in[13];
    const float* ff2_b = (const float*)d_in[14];
    float* out = (float*)d_out;

    float *x, *qkv, *tmp;
    int *rel, *seg;
    __half *hx, *hatt, *hff, *htok, *hqkvw, *houtw, *hff1w, *hff2w;
    cudaGetSymbolAddress((void**)&x,    g_x);
    cudaGetSymbolAddress((void**)&qkv,  g_qkv);
    cudaGetSymbolAddress((void**)&tmp,  g_tmp);
    cudaGetSymbolAddress((void**)&rel,  g_rel);
    cudaGetSymbolAddress((void**)&seg,  g_seg);
    cudaGetSymbolAddress((void**)&hx,   h_x);
    cudaGetSymbolAddress((void**)&hatt, h_att);
    cudaGetSymbolAddress((void**)&hff,  h_ff);
    cudaGetSymbolAddress((void**)&htok, h_tok);
    cudaGetSymbolAddress((void**)&hqkvw, h_qkvw);
    cudaGetSymbolAddress((void**)&houtw, h_outw);
    cudaGetSymbolAddress((void**)&hff1w, h_ff1w);
    cudaGetSymbolAddress((void**)&hff2w, h_ff2w);

    cudaFuncSetAttribute(attn_tile_kernel,
        cudaFuncAttributeMaxDynamicSharedMemorySize, ATTN_SMEM);

    // operand conversions (deterministic, every launch)
    conv(tok,   htok,  (long)VV*DD);
    conv(qkv_w, hqkvw, (long)NLAY*3*DD*DD);
    conv(out_w, houtw, (long)NLAY*DD*DD);
    conv(ff1_w, hff1w, (long)NLAY*DFFN*DD);
    conv(ff2_w, hff2w, (long)NLAY*DD*DFFN);

    meta_kernel<<<BB, 32>>>(ids, rel, seg);
    embed_kernel<<<ROWS, 256>>>(ids, rel, tok, pos, x, hx);

    const int MT = ROWS / 128;  // 16, fast axis

    for (int l = 0; l < NLAY; l++) {
        gemm_h<false,false><<<dim3(MT, 3*DD/128), 256>>>(
            hx, hqkvw + (size_t)l*3*DD*DD, qkv_b + (size_t)l*3*DD, qkv,
            ROWS, 3*DD, DD);

        attn_tile_kernel<<<dim3(LL/64, HH, BB), 256, ATTN_SMEM>>>(qkv, seg, hatt);

        gemm_h<false,false><<<dim3(MT, DD/128), 256>>>(
            hatt, houtw + (size_t)l*DD*DD, out_b + (size_t)l*DD, tmp,
            ROWS, DD, DD);

        add_ln_kernel<<<ROWS, 256>>>(x, tmp, ln1_w + (size_t)l*DD, ln1_b + (size_t)l*DD, hx);

        gemm_h<true,true><<<dim3(MT, DFFN/128), 256>>>(
            hx, hff1w + (size_t)l*DFFN*DD, ff1_b + (size_t)l*DFFN, hff,
            ROWS, DFFN, DD);

        gemm_h<false,false><<<dim3(MT, DD/128), 256>>>(
            hff, hff2w + (size_t)l*DD*DFFN, ff2_b + (size_t)l*DD, tmp,
            ROWS, DD, DFFN);

        add_ln_kernel<<<ROWS, 256>>>(x, tmp, ln2_w + (size_t)l*DD, ln2_b + (size_t)l*DD, hx);
    }

    gemm_h<false,false><<<dim3(MT, (VV + 127)/128), 256>>>(
        hx, htok, nullptr, out, ROWS, VV, DD);
}

// round 10
// speedup vs baseline: 1.3128x; 1.1748x over previous
#include <cuda_runtime.h>
#include <cuda_fp16.h>
#include <math.h>
#include <stdint.h>

// Problem constants
#define BB   2
#define LL   1024
#define DD   768
#define HH   12
#define HD   64
#define NLAY 2
#define DFFN 3072
#define VV   50257
#define EOS_ID 50256
#define ROWS (BB*LL)          // 2048

// ---------------------------------------------------------------------------
// Static scratch
// ---------------------------------------------------------------------------
__device__ float  g_x[ROWS*DD];
__device__ float  g_qkv[ROWS*3*DD];
__device__ float  g_tmp[ROWS*DD];
__device__ int    g_rel[ROWS];
__device__ int    g_seg[ROWS];
// fp16 operands
__device__ __half h_x[ROWS*DD];
__device__ __half h_att[ROWS*DD];
__device__ __half h_ff[ROWS*DFFN];
__device__ __half h_tok[VV*DD];
__device__ __half h_qkvw[NLAY*3*DD*DD];
__device__ __half h_outw[NLAY*DD*DD];
__device__ __half h_ff1w[NLAY*DFFN*DD];
__device__ __half h_ff2w[NLAY*DD*DFFN];

__device__ __forceinline__ uint32_t smem_u32(const void* p) {
    uint32_t a;
    asm("{ .reg .u64 t; cvta.to.shared.u64 t, %1; cvt.u32.u64 %0, t; }"
        : "=r"(a) : "l"(p));
    return a;
}

__device__ __forceinline__ uint32_t packh2(float x, float y) {
    __half2 h = __floats2half2_rn(x, y);
    return *reinterpret_cast<uint32_t*>(&h);
}

__device__ __forceinline__ void ldsm_x4(uint32_t addr, uint32_t& r0, uint32_t& r1,
                                        uint32_t& r2, uint32_t& r3) {
    asm volatile("ldmatrix.sync.aligned.m8n8.x4.shared.b16 {%0,%1,%2,%3}, [%4];"
                 : "=r"(r0), "=r"(r1), "=r"(r2), "=r"(r3) : "r"(addr));
}

__device__ __forceinline__ void ldsm_x4_t(uint32_t addr, uint32_t& r0, uint32_t& r1,
                                          uint32_t& r2, uint32_t& r3) {
    asm volatile("ldmatrix.sync.aligned.m8n8.x4.trans.shared.b16 {%0,%1,%2,%3}, [%4];"
                 : "=r"(r0), "=r"(r1), "=r"(r2), "=r"(r3) : "r"(addr));
}

#define MMA16816(d, a0,a1,a2,a3, b0,b1) \
    asm volatile( \
        "mma.sync.aligned.m16n8k16.row.col.f32.f16.f16.f32 " \
        "{%0,%1,%2,%3}, {%4,%5,%6,%7}, {%8,%9}, {%0,%1,%2,%3};\n" \
        : "+f"((d)[0]), "+f"((d)[1]), "+f"((d)[2]), "+f"((d)[3]) \
        : "r"(a0), "r"(a1), "r"(a2), "r"(a3), "r"(b0), "r"(b1))

// ---------------------------------------------------------------------------
// fp32 -> fp16 conversion
// ---------------------------------------------------------------------------
__global__ void f2h_kernel(const float* __restrict__ s, __half* __restrict__ d, int n) {
    int i = (blockIdx.x * blockDim.x + threadIdx.x) * 4;
    if (i < n) {
        float4 v = *reinterpret_cast<const float4*>(s + i);
        *reinterpret_cast<uint2*>(d + i) =
            make_uint2(packh2(v.x, v.y), packh2(v.z, v.w));
    }
}

// ---------------------------------------------------------------------------
// Meta + embedding
// ---------------------------------------------------------------------------
__global__ void meta_kernel(const int* __restrict__ ids, int* __restrict__ rel,
                            int* __restrict__ seg) {
    int b = blockIdx.x;
    if (threadIdx.x != 0) return;
    int last = 0, s = 0;
    for (int l = 0; l < LL; l++) {
        int id = ids[b*LL + l];
        if (id == EOS_ID) { last = l; s += 1; }
        rel[b*LL + l] = l - last;
        seg[b*LL + l] = s;
    }
}

__global__ void embed_kernel(const int* __restrict__ ids, const int* __restrict__ rel,
                             const float* __restrict__ tok, const float* __restrict__ pos,
                             float* __restrict__ x, __half* __restrict__ hx) {
    int row = blockIdx.x;
    int id = ids[row];
    int r  = rel[row];
    const float* t = tok + (size_t)id * DD;
    const float* p = pos + (size_t)r  * DD;
    const float sc = 27.712812921102035f;  // sqrt(768)
    for (int i = threadIdx.x; i < DD; i += blockDim.x) {
        float v = t[i] * sc + p[i];
        x[(size_t)row*DD + i]  = v;
        hx[(size_t)row*DD + i] = __float2half(v);
    }
}

#define HSTR 40   // halves per smem row for GEMM (32 data + 8 pad)

// ---------------------------------------------------------------------------
// FP16-operand GEMM (unchanged from R9): C = A @ B^T (+bias)(+GELU)
// ---------------------------------------------------------------------------
template<bool GELU, bool OUTH>
__global__ __launch_bounds__(256, 2)
void gemm_h(const __half* __restrict__ A, const __half* __restrict__ B,
            const float* __restrict__ bias, void* __restrict__ Cv,
            int M, int N, int K) {
    __shared__ __align__(16) __half SA[2][128*HSTR];
    __shared__ __align__(16) __half SB[2][128*HSTR];

    const int bm = blockIdx.x * 128;
    const int bn = blockIdx.y * 128;
    const int tid  = threadIdx.x;
    const int warp = tid >> 5;
    const int lane = tid & 31;
    const int grp  = lane >> 2;
    const int qid  = lane & 3;

    const int wm = (warp >> 1) * 32;
    const int wn = (warp & 1) * 64;

    const int lrow  = lane & 15;
    const int lcol8 = (lane >> 4) << 3;
    uint32_t aoff[2], boff[4];
#pragma unroll
    for (int i = 0; i < 2; i++)
        aoff[i] = ((wm + i*16 + lrow) * HSTR + lcol8) * 2;
#pragma unroll
    for (int p = 0; p < 4; p++)
        boff[p] = ((wn + p*16 + lrow) * HSTR + lcol8) * 2;

    const uint32_t sa0 = smem_u32(&SA[0][0]), sa1 = smem_u32(&SA[1][0]);
    const uint32_t sb0 = smem_u32(&SB[0][0]), sb1 = smem_u32(&SB[1][0]);

    float acc[2][8][4];
#pragma unroll
    for (int i = 0; i < 2; i++)
#pragma unroll
        for (int j = 0; j < 8; j++)
#pragma unroll
            for (int c = 0; c < 4; c++) acc[i][j][c] = 0.f;

    const int ntiles = K >> 5;
    uint4 rA[2], rB[2];
    const uint4 zero4 = make_uint4(0u, 0u, 0u, 0u);

#pragma unroll
    for (int i = 0; i < 2; i++) {
        int idx = tid + (i << 8);
        int row = idx >> 2;
        int s8  = (idx & 3) << 3;
        rA[i] = *reinterpret_cast<const uint4*>(A + (size_t)(bm + row) * K + s8);
        int gn = bn + row;
        rB[i] = (gn < N) ? *reinterpret_cast<const uint4*>(B + (size_t)gn * K + s8)
                         : zero4;
    }
#pragma unroll
    for (int i = 0; i < 2; i++) {
        int idx = tid + (i << 8);
        int row = idx >> 2;
        int s8  = (idx & 3) << 3;
        *reinterpret_cast<uint4*>(&SA[0][row*HSTR + s8]) = rA[i];
        *reinterpret_cast<uint4*>(&SB[0][row*HSTR + s8]) = rB[i];
    }
    __syncthreads();

    for (int t = 0; t < ntiles; t++) {
        const int cb = t & 1;
        const bool more = (t + 1 < ntiles);

        if (more) {
            int kt = (t + 1) << 5;
#pragma unroll
            for (int i = 0; i < 2; i++) {
                int idx = tid + (i << 8);
                int row = idx >> 2;
                int s8  = (idx & 3) << 3;
                rA[i] = *reinterpret_cast<const uint4*>(A + (size_t)(bm + row) * K + kt + s8);
                int gn = bn + row;
                rB[i] = (gn < N) ? *reinterpret_cast<const uint4*>(B + (size_t)gn * K + kt + s8)
                                 : zero4;
            }
        }

        const uint32_t sa = cb ? sa1 : sa0;
        const uint32_t sb = cb ? sb1 : sb0;
#pragma unroll
        for (int ks = 0; ks < 2; ks++) {
            const uint32_t kb = ks * 32;
            uint32_t af[2][4];
#pragma unroll
            for (int i = 0; i < 2; i++)
                ldsm_x4(sa + aoff[i] + kb, af[i][0], af[i][1], af[i][2], af[i][3]);
#pragma unroll
            for (int p = 0; p < 4; p++) {
                uint32_t bf[4];
                ldsm_x4(sb + boff[p] + kb, bf[0], bf[1], bf[2], bf[3]);
#pragma unroll
                for (int i = 0; i < 2; i++) {
                    MMA16816(acc[i][2*p],   af[i][0], af[i][1], af[i][2], af[i][3], bf[0], bf[2]);
                    MMA16816(acc[i][2*p+1], af[i][0], af[i][1], af[i][2], af[i][3], bf[1], bf[3]);
                }
            }
        }

        if (more) {
            const int nb = (t + 1) & 1;
#pragma unroll
            for (int i = 0; i < 2; i++) {
                int idx = tid + (i << 8);
                int row = idx >> 2;
                int s8  = (idx & 3) << 3;
                *reinterpret_cast<uint4*>(&SA[nb][row*HSTR + s8]) = rA[i];
                *reinterpret_cast<uint4*>(&SB[nb][row*HSTR + s8]) = rB[i];
            }
        }
        __syncthreads();
    }

    float*  Cf = reinterpret_cast<float*>(Cv);
    __half* Ch = reinterpret_cast<__half*>(Cv);
    const bool evenN = (N & 1) == 0;
#pragma unroll
    for (int i = 0; i < 2; i++) {
#pragma unroll
        for (int j = 0; j < 8; j++) {
#pragma unroll
            for (int pr = 0; pr < 2; pr++) {
                int row = bm + wm + i*16 + grp + pr*8;
                int col = bn + wn + j*8 + (qid << 1);
                float v0 = acc[i][j][2*pr + 0];
                float v1 = acc[i][j][2*pr + 1];
                if (bias) { v0 += bias[col]; if (col + 1 < N) v1 += bias[col + 1]; }
                if (GELU) {
                    v0 = 0.5f * v0 * (1.0f + erff(v0 * 0.7071067811865475f));
                    v1 = 0.5f * v1 * (1.0f + erff(v1 * 0.7071067811865475f));
                }
                size_t base = (size_t)row * N + col;
                if (OUTH) {
                    if (col + 1 < N) {
                        *reinterpret_cast<uint32_t*>(&Ch[base]) = packh2(v0, v1);
                    } else if (col < N) {
                        Ch[base] = __float2half(v0);
                    }
                } else {
                    if (col + 1 < N) {
                        if (evenN) *reinterpret_cast<float2*>(&Cf[base]) = make_float2(v0, v1);
                        else { Cf[base] = v0; Cf[base + 1] = v1; }
                    } else if (col < N) {
                        Cf[base] = v0;
                    }
                }
            }
        }
    }
}

// ---------------------------------------------------------------------------
// Tensor-core flash attention: q-tile 128, kv-tile 64, 8 warps x 16 q-rows.
// fp16 mma (fp32 accum), fp32 online softmax, S->P repack in registers.
// Scale 1/8 folded into Q at load. Output fp16 (feeds out-proj GEMM A).
// ---------------------------------------------------------------------------
#define ASTR 72   // halves per attention smem row (64 data + 8 pad)

__global__ __launch_bounds__(256, 2)
void attn_mma_kernel(const float* __restrict__ qkv, const int* __restrict__ seg,
                     __half* __restrict__ o) {
    __shared__ __align__(16) __half Qh[128*ASTR];
    __shared__ __align__(16) __half Kh[64*ASTR];
    __shared__ __align__(16) __half Vh[64*ASTR];
    __shared__ int sseg[64];

    const int qt = blockIdx.x;       // 0..7
    const int h  = blockIdx.y;
    const int b  = blockIdx.z;
    const int tid  = threadIdx.x;
    const int warp = tid >> 5;
    const int lane = tid & 31;
    const int grp  = lane >> 2;      // 0..7
    const int qid  = lane & 3;       // 0..3
    const int q0 = qt * 128;

    const uint32_t qbase = smem_u32(Qh);
    const uint32_t kbase = smem_u32(Kh);
    const uint32_t vbase = smem_u32(Vh);
    const int lrow  = lane & 15;
    const int lcol8 = (lane >> 4) << 3;

    // load Q (scaled) -> fp16 smem
#pragma unroll
    for (int i = 0; i < 8; i++) {
        int idx = tid + (i << 8);
        int r  = idx >> 4;
        int c4 = (idx & 15) << 2;
        float4 v = *reinterpret_cast<const float4*>(
            qkv + (size_t)(b*LL + q0 + r)*(3*DD) + h*HD + c4);
        *reinterpret_cast<uint2*>(&Qh[r*ASTR + c4]) =
            make_uint2(packh2(v.x*0.125f, v.y*0.125f), packh2(v.z*0.125f, v.w*0.125f));
    }

    // per-thread q rows
    const int qg0 = q0 + warp*16 + grp;
    const int qg1 = qg0 + 8;
    const int qseg0 = seg[b*LL + qg0];
    const int qseg1 = seg[b*LL + qg1];

    float m0 = -1e30f, m1 = -1e30f, l0 = 0.f, l1 = 0.f;
    float O[8][4];
#pragma unroll
    for (int j = 0; j < 8; j++)
#pragma unroll
        for (int c = 0; c < 4; c++) O[j][c] = 0.f;

    const int ntiles = 2*qt + 2;
    for (int kt = 0; kt < ntiles; kt++) {
        const int k0 = kt * 64;
        __syncthreads();   // previous tile fully consumed
        // load K, V -> fp16 smem
#pragma unroll
        for (int i = 0; i < 4; i++) {
            int idx = tid + (i << 8);
            int r  = idx >> 4;
            int c4 = (idx & 15) << 2;
            const float* base = qkv + (size_t)(b*LL + k0 + r)*(3*DD) + h*HD + c4;
            float4 kv = *reinterpret_cast<const float4*>(base + DD);
            *reinterpret_cast<uint2*>(&Kh[r*ASTR + c4]) =
                make_uint2(packh2(kv.x, kv.y), packh2(kv.z, kv.w));
            float4 vv = *reinterpret_cast<const float4*>(base + 2*DD);
            *reinterpret_cast<uint2*>(&Vh[r*ASTR + c4]) =
                make_uint2(packh2(vv.x, vv.y), packh2(vv.z, vv.w));
        }
        if (tid < 64) sseg[tid] = seg[b*LL + k0 + tid];
        __syncthreads();

        // S = Q K^T  (16q x 64k per warp)
        float s[8][4];
#pragma unroll
        for (int j = 0; j < 8; j++)
#pragma unroll
            for (int c = 0; c < 4; c++) s[j][c] = 0.f;
#pragma unroll
        for (int ks = 0; ks < 4; ks++) {
            uint32_t aq[4];
            ldsm_x4(qbase + ((warp*16 + lrow)*ASTR + ks*16 + lcol8)*2,
                    aq[0], aq[1], aq[2], aq[3]);
#pragma unroll
            for (int p = 0; p < 4; p++) {
                uint32_t bf[4];
                ldsm_x4(kbase + ((p*16 + lrow)*ASTR + ks*16 + lcol8)*2,
                        bf[0], bf[1], bf[2], bf[3]);
                MMA16816(s[2*p],   aq[0], aq[1], aq[2], aq[3], bf[0], bf[2]);
                MMA16816(s[2*p+1], aq[0], aq[1], aq[2], aq[3], bf[1], bf[3]);
            }
        }

        // mask + online softmax (rows qg0, qg1)
        float mt0 = -1e30f, mt1 = -1e30f;
#pragma unroll
        for (int j = 0; j < 8; j++) {
            int kg0 = k0 + 8*j + 2*qid;
            int sg0 = sseg[8*j + 2*qid];
            int sg1 = sseg[8*j + 2*qid + 1];
            s[j][0] = (kg0     <= qg0 && sg0 == qseg0) ? s[j][0] : -1e30f;
            s[j][1] = (kg0 + 1 <= qg0 && sg1 == qseg0) ? s[j][1] : -1e30f;
            s[j][2] = (kg0     <= qg1 && sg0 == qseg1) ? s[j][2] : -1e30f;
            s[j][3] = (kg0 + 1 <= qg1 && sg1 == qseg1) ? s[j][3] : -1e30f;
            mt0 = fmaxf(mt0, fmaxf(s[j][0], s[j][1]));
            mt1 = fmaxf(mt1, fmaxf(s[j][2], s[j][3]));
        }
#pragma unroll
        for (int off = 1; off < 4; off <<= 1) {
            mt0 = fmaxf(mt0, __shfl_xor_sync(0xffffffffu, mt0, off));
            mt1 = fmaxf(mt1, __shfl_xor_sync(0xffffffffu, mt1, off));
        }
        float mn0 = fmaxf(m0, mt0), mn1 = fmaxf(m1, mt1);
        float f0 = __expf(m0 - mn0), f1 = __expf(m1 - mn1);
        m0 = mn0; m1 = mn1;
        float rs0 = 0.f, rs1 = 0.f;
#pragma unroll
        for (int j = 0; j < 8; j++) {
            s[j][0] = __expf(s[j][0] - mn0);
            s[j][1] = __expf(s[j][1] - mn0);
            s[j][2] = __expf(s[j][2] - mn1);
            s[j][3] = __expf(s[j][3] - mn1);
            rs0 += s[j][0] + s[j][1];
            rs1 += s[j][2] + s[j][3];
            O[j][0] *= f0; O[j][1] *= f0;
            O[j][2] *= f1; O[j][3] *= f1;
        }
#pragma unroll
        for (int off = 1; off < 4; off <<= 1) {
            rs0 += __shfl_xor_sync(0xffffffffu, rs0, off);
            rs1 += __shfl_xor_sync(0xffffffffu, rs1, off);
        }
        l0 = l0 * f0 + rs0;
        l1 = l1 * f1 + rs1;

        // P (fp16 A-frags) directly from S registers
        uint32_t ap[4][4];
#pragma unroll
        for (int ks = 0; ks < 4; ks++) {
            ap[ks][0] = packh2(s[2*ks][0],   s[2*ks][1]);
            ap[ks][1] = packh2(s[2*ks][2],   s[2*ks][3]);
            ap[ks][2] = packh2(s[2*ks+1][0], s[2*ks+1][1]);
            ap[ks][3] = packh2(s[2*ks+1][2], s[2*ks+1][3]);
        }

        // O += P @ V   (V B-frags via ldmatrix.trans)
#pragma unroll
        for (int ks = 0; ks < 4; ks++) {
#pragma unroll
            for (int p = 0; p < 4; p++) {
                uint32_t bv[4];
                ldsm_x4_t(vbase + ((ks*16 + lrow)*ASTR + p*16 + lcol8)*2,
                          bv[0], bv[1], bv[2], bv[3]);
                MMA16816(O[2*p],   ap[ks][0], ap[ks][1], ap[ks][2], ap[ks][3], bv[0], bv[1]);
                MMA16816(O[2*p+1], ap[ks][0], ap[ks][1], ap[ks][2], ap[ks][3], bv[2], bv[3]);
            }
        }
    }

    // write fp16 output
    float inv0 = 1.0f / l0, inv1 = 1.0f / l1;
#pragma unroll
    for (int j = 0; j < 8; j++) {
        int col = h*HD + 8*j + 2*qid;
        *reinterpret_cast<uint32_t*>(&o[(size_t)(b*LL + qg0)*DD + col]) =
            packh2(O[j][0]*inv0, O[j][1]*inv0);
        *reinterpret_cast<uint32_t*>(&o[(size_t)(b*LL + qg1)*DD + col]) =
            packh2(O[j][2]*inv1, O[j][3]*inv1);
    }
}

// ---------------------------------------------------------------------------
// Block reduction + fused add+LN
// ---------------------------------------------------------------------------
__device__ __forceinline__ float block_sum256(float v, volatile float* red) {
#pragma unroll
    for (int o = 16; o; o >>= 1) v += __shfl_xor_sync(0xffffffffu, v, o);
    if ((threadIdx.x & 31) == 0) red[threadIdx.x >> 5] = v;
    __syncthreads();
    if (threadIdx.x == 0) {
        float s = red[0];
#pragma unroll
        for (int i = 1; i < 8; i++) s += red[i];
        red[0] = s;
    }
    __syncthreads();
    float r = red[0];
    __syncthreads();
    return r;
}

__global__ __launch_bounds__(256)
void add_ln_kernel(float* __restrict__ x, const float* __restrict__ r,
                   const float* __restrict__ w, const float* __restrict__ b,
                   __half* __restrict__ hx) {
    int row = blockIdx.x;
    int tid = threadIdx.x;
    __shared__ float buf[DD];
    __shared__ float red[8];

    float s = 0.f;
    for (int i = tid; i < DD; i += 256) {
        float v = x[(size_t)row*DD + i] + r[(size_t)row*DD + i];
        buf[i] = v;
        s += v;
    }
    __syncthreads();
    float mean = block_sum256(s, red) * (1.0f / DD);

    float vs = 0.f;
    for (int i = tid; i < DD; i += 256) {
        float d = buf[i] - mean;
        vs += d * d;
    }
    float var = block_sum256(vs, red) * (1.0f / DD);
    float inv = rsqrtf(var + 1e-5f);

    for (int i = tid; i < DD; i += 256) {
        float v = (buf[i] - mean) * inv * w[i] + b[i];
        x[(size_t)row*DD + i]  = v;
        hx[(size_t)row*DD + i] = __float2half(v);
    }
}

// ---------------------------------------------------------------------------
// Host launcher
// ---------------------------------------------------------------------------
static inline void conv(const float* s, __half* d, long n) {
    int blocks = (int)((n/4 + 255) / 256);
    f2h_kernel<<<blocks, 256>>>(s, d, (int)n);
}

extern "C" void kernel_launch(void* const* d_in, const int* in_sizes, int n_in,
                              void* d_out, int out_size) {
    const int*   ids   = (const int*)  d_in[0];
    const float* tok   = (const float*)d_in[1];
    const float* pos   = (const float*)d_in[2];
    const float* qkv_w = (const float*)d_in[3];
    const float* qkv_b = (const float*)d_in[4];
    const float* out_w = (const float*)d_in[5];
    const float* out_b = (const float*)d_in[6];
    const float* ln1_w = (const float*)d_in[7];
    const float* ln1_b = (const float*)d_in[8];
    const float* ln2_w = (const float*)d_in[9];
    const float* ln2_b = (const float*)d_in[10];
    const float* ff1_w = (const float*)d_in[11];
    const float* ff1_b = (const float*)d_in[12];
    const float* ff2_w = (const float*)d_in[13];
    const float* ff2_b = (const float*)d_in[14];
    float* out = (float*)d_out;

    float *x, *qkv, *tmp;
    int *rel, *seg;
    __half *hx, *hatt, *hff, *htok, *hqkvw, *houtw, *hff1w, *hff2w;
    cudaGetSymbolAddress((void**)&x,    g_x);
    cudaGetSymbolAddress((void**)&qkv,  g_qkv);
    cudaGetSymbolAddress((void**)&tmp,  g_tmp);
    cudaGetSymbolAddress((void**)&rel,  g_rel);
    cudaGetSymbolAddress((void**)&seg,  g_seg);
    cudaGetSymbolAddress((void**)&hx,   h_x);
    cudaGetSymbolAddress((void**)&hatt, h_att);
    cudaGetSymbolAddress((void**)&hff,  h_ff);
    cudaGetSymbolAddress((void**)&htok, h_tok);
    cudaGetSymbolAddress((void**)&hqkvw, h_qkvw);
    cudaGetSymbolAddress((void**)&houtw, h_outw);
    cudaGetSymbolAddress((void**)&hff1w, h_ff1w);
    cudaGetSymbolAddress((void**)&hff2w, h_ff2w);

    // operand conversions (deterministic, every launch)
    conv(tok,   htok,  (long)VV*DD);
    conv(qkv_w, hqkvw, (long)NLAY*3*DD*DD);
    conv(out_w, houtw, (long)NLAY*DD*DD);
    conv(ff1_w, hff1w, (long)NLAY*DFFN*DD);
    conv(ff2_w, hff2w, (long)NLAY*DD*DFFN);

    meta_kernel<<<BB, 32>>>(ids, rel, seg);
    embed_kernel<<<ROWS, 256>>>(ids, rel, tok, pos, x, hx);

    const int MT = ROWS / 128;  // 16, fast axis

    for (int l = 0; l < NLAY; l++) {
        gemm_h<false,false><<<dim3(MT, 3*DD/128), 256>>>(
            hx, hqkvw + (size_t)l*3*DD*DD, qkv_b + (size_t)l*3*DD, qkv,
            ROWS, 3*DD, DD);

        attn_mma_kernel<<<dim3(LL/128, HH, BB), 256>>>(qkv, seg, hatt);

        gemm_h<false,false><<<dim3(MT, DD/128), 256>>>(
            hatt, houtw + (size_t)l*DD*DD, out_b + (size_t)l*DD, tmp,
            ROWS, DD, DD);

        add_ln_kernel<<<ROWS, 256>>>(x, tmp, ln1_w + (size_t)l*DD, ln1_b + (size_t)l*DD, hx);

        gemm_h<true,true><<<dim3(MT, DFFN/128), 256>>>(
            hx, hff1w + (size_t)l*DFFN*DD, ff1_b + (size_t)l*DFFN, hff,
            ROWS, DFFN, DD);

        gemm_h<false,false><<<dim3(MT, DD/128), 256>>>(
            hff, hff2w + (size_t)l*DD*DFFN, ff2_b + (size_t)l*DD, tmp,
            ROWS, DD, DFFN);

        add_ln_kernel<<<ROWS, 256>>>(x, tmp, ln2_w + (size_t)l*DD, ln2_b + (size_t)l*DD, hx);
    }

    gemm_h<false,false><<<dim3(MT, (VV + 127)/128), 256>>>(
        hx, htok, nullptr, out, ROWS, VV, DD);
}

// round 11
// speedup vs baseline: 1.3232x; 1.0080x over previous
#include <cuda_runtime.h>
#include <cuda_fp16.h>
#include <math.h>
#include <stdint.h>

// Problem constants
#define BB   2
#define LL   1024
#define DD   768
#define HH   12
#define HD   64
#define NLAY 2
#define DFFN 3072
#define VV   50257
#define EOS_ID 50256
#define ROWS (BB*LL)          // 2048

// ---------------------------------------------------------------------------
// Static scratch
// ---------------------------------------------------------------------------
__device__ float  g_x[ROWS*DD];
__device__ float  g_tmp[ROWS*DD];
__device__ int    g_rel[ROWS];
__device__ int    g_seg[ROWS];
// fp16 tensors
__device__ __half h_qkv[ROWS*3*DD];
__device__ __half h_x[ROWS*DD];
__device__ __half h_att[ROWS*DD];
__device__ __half h_ff[ROWS*DFFN];
__device__ __half h_tok[VV*DD];
__device__ __half h_qkvw[NLAY*3*DD*DD];
__device__ __half h_outw[NLAY*DD*DD];
__device__ __half h_ff1w[NLAY*DFFN*DD];
__device__ __half h_ff2w[NLAY*DD*DFFN];

__device__ __forceinline__ uint32_t smem_u32(const void* p) {
    uint32_t a;
    asm("{ .reg .u64 t; cvta.to.shared.u64 t, %1; cvt.u32.u64 %0, t; }"
        : "=r"(a) : "l"(p));
    return a;
}

__device__ __forceinline__ uint32_t packh2(float x, float y) {
    __half2 h = __floats2half2_rn(x, y);
    return *reinterpret_cast<uint32_t*>(&h);
}

__device__ __forceinline__ void ldsm_x4(uint32_t addr, uint32_t& r0, uint32_t& r1,
                                        uint32_t& r2, uint32_t& r3) {
    asm volatile("ldmatrix.sync.aligned.m8n8.x4.shared.b16 {%0,%1,%2,%3}, [%4];"
                 : "=r"(r0), "=r"(r1), "=r"(r2), "=r"(r3) : "r"(addr));
}

__device__ __forceinline__ void ldsm_x4_t(uint32_t addr, uint32_t& r0, uint32_t& r1,
                                          uint32_t& r2, uint32_t& r3) {
    asm volatile("ldmatrix.sync.aligned.m8n8.x4.trans.shared.b16 {%0,%1,%2,%3}, [%4];"
                 : "=r"(r0), "=r"(r1), "=r"(r2), "=r"(r3) : "r"(addr));
}

#define MMA16816(d, a0,a1,a2,a3, b0,b1) \
    asm volatile( \
        "mma.sync.aligned.m16n8k16.row.col.f32.f16.f16.f32 " \
        "{%0,%1,%2,%3}, {%4,%5,%6,%7}, {%8,%9}, {%0,%1,%2,%3};\n" \
        : "+f"((d)[0]), "+f"((d)[1]), "+f"((d)[2]), "+f"((d)[3]) \
        : "r"(a0), "r"(a1), "r"(a2), "r"(a3), "r"(b0), "r"(b1))

// ---------------------------------------------------------------------------
// fp32 -> fp16 conversion
// ---------------------------------------------------------------------------
__global__ void f2h_kernel(const float* __restrict__ s, __half* __restrict__ d, int n) {
    int i = (blockIdx.x * blockDim.x + threadIdx.x) * 4;
    if (i < n) {
        float4 v = *reinterpret_cast<const float4*>(s + i);
        *reinterpret_cast<uint2*>(d + i) =
            make_uint2(packh2(v.x, v.y), packh2(v.z, v.w));
    }
}

// ---------------------------------------------------------------------------
// Meta + embedding
// ---------------------------------------------------------------------------
__global__ void meta_kernel(const int* __restrict__ ids, int* __restrict__ rel,
                            int* __restrict__ seg) {
    int b = blockIdx.x;
    if (threadIdx.x != 0) return;
    int last = 0, s = 0;
    for (int l = 0; l < LL; l++) {
        int id = ids[b*LL + l];
        if (id == EOS_ID) { last = l; s += 1; }
        rel[b*LL + l] = l - last;
        seg[b*LL + l] = s;
    }
}

__global__ void embed_kernel(const int* __restrict__ ids, const int* __restrict__ rel,
                             const float* __restrict__ tok, const float* __restrict__ pos,
                             float* __restrict__ x, __half* __restrict__ hx) {
    int row = blockIdx.x;
    int id = ids[row];
    int r  = rel[row];
    const float* t = tok + (size_t)id * DD;
    const float* p = pos + (size_t)r  * DD;
    const float sc = 27.712812921102035f;  // sqrt(768)
    for (int i = threadIdx.x; i < DD; i += blockDim.x) {
        float v = t[i] * sc + p[i];
        x[(size_t)row*DD + i]  = v;
        hx[(size_t)row*DD + i] = __float2half(v);
    }
}

#define HSTR 40   // halves per smem row for GEMM (32 data + 8 pad)

// ---------------------------------------------------------------------------
// FP16-operand GEMM: C = A @ B^T (+bias)(+GELU). OUTH -> fp16 C (N even).
// ---------------------------------------------------------------------------
template<bool GELU, bool OUTH>
__global__ __launch_bounds__(256, 2)
void gemm_h(const __half* __restrict__ A, const __half* __restrict__ B,
            const float* __restrict__ bias, void* __restrict__ Cv,
            int M, int N, int K) {
    __shared__ __align__(16) __half SA[2][128*HSTR];
    __shared__ __align__(16) __half SB[2][128*HSTR];

    const int bm = blockIdx.x * 128;
    const int bn = blockIdx.y * 128;
    const int tid  = threadIdx.x;
    const int warp = tid >> 5;
    const int lane = tid & 31;
    const int grp  = lane >> 2;
    const int qid  = lane & 3;

    const int wm = (warp >> 1) * 32;
    const int wn = (warp & 1) * 64;

    const int lrow  = lane & 15;
    const int lcol8 = (lane >> 4) << 3;
    uint32_t aoff[2], boff[4];
#pragma unroll
    for (int i = 0; i < 2; i++)
        aoff[i] = ((wm + i*16 + lrow) * HSTR + lcol8) * 2;
#pragma unroll
    for (int p = 0; p < 4; p++)
        boff[p] = ((wn + p*16 + lrow) * HSTR + lcol8) * 2;

    const uint32_t sa0 = smem_u32(&SA[0][0]), sa1 = smem_u32(&SA[1][0]);
    const uint32_t sb0 = smem_u32(&SB[0][0]), sb1 = smem_u32(&SB[1][0]);

    float acc[2][8][4];
#pragma unroll
    for (int i = 0; i < 2; i++)
#pragma unroll
        for (int j = 0; j < 8; j++)
#pragma unroll
            for (int c = 0; c < 4; c++) acc[i][j][c] = 0.f;

    const int ntiles = K >> 5;
    uint4 rA[2], rB[2];
    const uint4 zero4 = make_uint4(0u, 0u, 0u, 0u);

#pragma unroll
    for (int i = 0; i < 2; i++) {
        int idx = tid + (i << 8);
        int row = idx >> 2;
        int s8  = (idx & 3) << 3;
        rA[i] = *reinterpret_cast<const uint4*>(A + (size_t)(bm + row) * K + s8);
        int gn = bn + row;
        rB[i] = (gn < N) ? *reinterpret_cast<const uint4*>(B + (size_t)gn * K + s8)
                         : zero4;
    }
#pragma unroll
    for (int i = 0; i < 2; i++) {
        int idx = tid + (i << 8);
        int row = idx >> 2;
        int s8  = (idx & 3) << 3;
        *reinterpret_cast<uint4*>(&SA[0][row*HSTR + s8]) = rA[i];
        *reinterpret_cast<uint4*>(&SB[0][row*HSTR + s8]) = rB[i];
    }
    __syncthreads();

    for (int t = 0; t < ntiles; t++) {
        const int cb = t & 1;
        const bool more = (t + 1 < ntiles);

        if (more) {
            int kt = (t + 1) << 5;
#pragma unroll
            for (int i = 0; i < 2; i++) {
                int idx = tid + (i << 8);
                int row = idx >> 2;
                int s8  = (idx & 3) << 3;
                rA[i] = *reinterpret_cast<const uint4*>(A + (size_t)(bm + row) * K + kt + s8);
                int gn = bn + row;
                rB[i] = (gn < N) ? *reinterpret_cast<const uint4*>(B + (size_t)gn * K + kt + s8)
                                 : zero4;
            }
        }

        const uint32_t sa = cb ? sa1 : sa0;
        const uint32_t sb = cb ? sb1 : sb0;
#pragma unroll
        for (int ks = 0; ks < 2; ks++) {
            const uint32_t kb = ks * 32;
            uint32_t af[2][4];
#pragma unroll
            for (int i = 0; i < 2; i++)
                ldsm_x4(sa + aoff[i] + kb, af[i][0], af[i][1], af[i][2], af[i][3]);
#pragma unroll
            for (int p = 0; p < 4; p++) {
                uint32_t bf[4];
                ldsm_x4(sb + boff[p] + kb, bf[0], bf[1], bf[2], bf[3]);
#pragma unroll
                for (int i = 0; i < 2; i++) {
                    MMA16816(acc[i][2*p],   af[i][0], af[i][1], af[i][2], af[i][3], bf[0], bf[2]);
                    MMA16816(acc[i][2*p+1], af[i][0], af[i][1], af[i][2], af[i][3], bf[1], bf[3]);
                }
            }
        }

        if (more) {
            const int nb = (t + 1) & 1;
#pragma unroll
            for (int i = 0; i < 2; i++) {
                int idx = tid + (i << 8);
                int row = idx >> 2;
                int s8  = (idx & 3) << 3;
                *reinterpret_cast<uint4*>(&SA[nb][row*HSTR + s8]) = rA[i];
                *reinterpret_cast<uint4*>(&SB[nb][row*HSTR + s8]) = rB[i];
            }
        }
        __syncthreads();
    }

    float*  Cf = reinterpret_cast<float*>(Cv);
    __half* Ch = reinterpret_cast<__half*>(Cv);
    const bool evenN = (N & 1) == 0;
#pragma unroll
    for (int i = 0; i < 2; i++) {
#pragma unroll
        for (int j = 0; j < 8; j++) {
#pragma unroll
            for (int pr = 0; pr < 2; pr++) {
                int row = bm + wm + i*16 + grp + pr*8;
                int col = bn + wn + j*8 + (qid << 1);
                float v0 = acc[i][j][2*pr + 0];
                float v1 = acc[i][j][2*pr + 1];
                if (bias) { v0 += bias[col]; if (col + 1 < N) v1 += bias[col + 1]; }
                if (GELU) {
                    v0 = 0.5f * v0 * (1.0f + erff(v0 * 0.7071067811865475f));
                    v1 = 0.5f * v1 * (1.0f + erff(v1 * 0.7071067811865475f));
                }
                size_t base = (size_t)row * N + col;
                if (OUTH) {
                    if (col + 1 < N) {
                        *reinterpret_cast<uint32_t*>(&Ch[base]) = packh2(v0, v1);
                    } else if (col < N) {
                        Ch[base] = __float2half(v0);
                    }
                } else {
                    if (col + 1 < N) {
                        if (evenN) *reinterpret_cast<float2*>(&Cf[base]) = make_float2(v0, v1);
                        else { Cf[base] = v0; Cf[base + 1] = v1; }
                    } else if (col < N) {
                        Cf[base] = v0;
                    }
                }
            }
        }
    }
}

// ---------------------------------------------------------------------------
// Tensor-core flash attention, fp16 qkv input (q-tile 128, kv-tile 64).
// 8 warps x 16 q-rows; fp16 mma, fp32 softmax; scale 1/8 applied in fp16
// (power of two -> exact). Output fp16.
// ---------------------------------------------------------------------------
#define ASTR 72   // halves per attention smem row (64 data + 8 pad)

__global__ __launch_bounds__(256, 2)
void attn_mma_kernel(const __half* __restrict__ qkv, const int* __restrict__ seg,
                     __half* __restrict__ o) {
    __shared__ __align__(16) __half Qh[128*ASTR];
    __shared__ __align__(16) __half Kh[64*ASTR];
    __shared__ __align__(16) __half Vh[64*ASTR];
    __shared__ int sseg[64];

    const int qt = blockIdx.x;       // 0..7
    const int h  = blockIdx.y;
    const int b  = blockIdx.z;
    const int tid  = threadIdx.x;
    const int warp = tid >> 5;
    const int lane = tid & 31;
    const int grp  = lane >> 2;      // 0..7
    const int qid  = lane & 3;       // 0..3
    const int q0 = qt * 128;

    const uint32_t qbase = smem_u32(Qh);
    const uint32_t kbase = smem_u32(Kh);
    const uint32_t vbase = smem_u32(Vh);
    const int lrow  = lane & 15;
    const int lcol8 = (lane >> 4) << 3;

    // load Q (scaled by exact 0.125 in fp16) -> smem
    const __half2 sc2 = __floats2half2_rn(0.125f, 0.125f);
#pragma unroll
    for (int i = 0; i < 4; i++) {
        int idx = tid + (i << 8);         // 0..1023
        int r  = idx >> 3;                // 0..127
        int c8 = (idx & 7) << 3;          // 0..56 step 8
        uint4 v = *reinterpret_cast<const uint4*>(
            qkv + (size_t)(b*LL + q0 + r)*(3*DD) + h*HD + c8);
        __half2* hv = reinterpret_cast<__half2*>(&v);
#pragma unroll
        for (int c = 0; c < 4; c++) hv[c] = __hmul2(hv[c], sc2);
        *reinterpret_cast<uint4*>(&Qh[r*ASTR + c8]) = v;
    }

    const int qg0 = q0 + warp*16 + grp;
    const int qg1 = qg0 + 8;
    const int qseg0 = seg[b*LL + qg0];
    const int qseg1 = seg[b*LL + qg1];

    float m0 = -1e30f, m1 = -1e30f, l0 = 0.f, l1 = 0.f;
    float O[8][4];
#pragma unroll
    for (int j = 0; j < 8; j++)
#pragma unroll
        for (int c = 0; c < 4; c++) O[j][c] = 0.f;

    const int ntiles = 2*qt + 2;
    for (int kt = 0; kt < ntiles; kt++) {
        const int k0 = kt * 64;
        __syncthreads();
        // load K, V (fp16, direct copy) -> smem
#pragma unroll
        for (int i = 0; i < 2; i++) {
            int idx = tid + (i << 8);     // 0..511
            int r  = idx >> 3;            // 0..63
            int c8 = (idx & 7) << 3;
            const __half* base = qkv + (size_t)(b*LL + k0 + r)*(3*DD) + h*HD + c8;
            *reinterpret_cast<uint4*>(&Kh[r*ASTR + c8]) =
                *reinterpret_cast<const uint4*>(base + DD);
            *reinterpret_cast<uint4*>(&Vh[r*ASTR + c8]) =
                *reinterpret_cast<const uint4*>(base + 2*DD);
        }
        if (tid < 64) sseg[tid] = seg[b*LL + k0 + tid];
        __syncthreads();

        // S = Q K^T
        float s[8][4];
#pragma unroll
        for (int j = 0; j < 8; j++)
#pragma unroll
            for (int c = 0; c < 4; c++) s[j][c] = 0.f;
#pragma unroll
        for (int ks = 0; ks < 4; ks++) {
            uint32_t aq[4];
            ldsm_x4(qbase + ((warp*16 + lrow)*ASTR + ks*16 + lcol8)*2,
                    aq[0], aq[1], aq[2], aq[3]);
#pragma unroll
            for (int p = 0; p < 4; p++) {
                uint32_t bf[4];
                ldsm_x4(kbase + ((p*16 + lrow)*ASTR + ks*16 + lcol8)*2,
                        bf[0], bf[1], bf[2], bf[3]);
                MMA16816(s[2*p],   aq[0], aq[1], aq[2], aq[3], bf[0], bf[2]);
                MMA16816(s[2*p+1], aq[0], aq[1], aq[2], aq[3], bf[1], bf[3]);
            }
        }

        // mask + online softmax
        float mt0 = -1e30f, mt1 = -1e30f;
#pragma unroll
        for (int j = 0; j < 8; j++) {
            int kg0 = k0 + 8*j + 2*qid;
            int sg0 = sseg[8*j + 2*qid];
            int sg1 = sseg[8*j + 2*qid + 1];
            s[j][0] = (kg0     <= qg0 && sg0 == qseg0) ? s[j][0] : -1e30f;
            s[j][1] = (kg0 + 1 <= qg0 && sg1 == qseg0) ? s[j][1] : -1e30f;
            s[j][2] = (kg0     <= qg1 && sg0 == qseg1) ? s[j][2] : -1e30f;
            s[j][3] = (kg0 + 1 <= qg1 && sg1 == qseg1) ? s[j][3] : -1e30f;
            mt0 = fmaxf(mt0, fmaxf(s[j][0], s[j][1]));
            mt1 = fmaxf(mt1, fmaxf(s[j][2], s[j][3]));
        }
#pragma unroll
        for (int off = 1; off < 4; off <<= 1) {
            mt0 = fmaxf(mt0, __shfl_xor_sync(0xffffffffu, mt0, off));
            mt1 = fmaxf(mt1, __shfl_xor_sync(0xffffffffu, mt1, off));
        }
        float mn0 = fmaxf(m0, mt0), mn1 = fmaxf(m1, mt1);
        float f0 = __expf(m0 - mn0), f1 = __expf(m1 - mn1);
        m0 = mn0; m1 = mn1;
        float rs0 = 0.f, rs1 = 0.f;
#pragma unroll
        for (int j = 0; j < 8; j++) {
            s[j][0] = __expf(s[j][0] - mn0);
            s[j][1] = __expf(s[j][1] - mn0);
            s[j][2] = __expf(s[j][2] - mn1);
            s[j][3] = __expf(s[j][3] - mn1);
            rs0 += s[j][0] + s[j][1];
            rs1 += s[j][2] + s[j][3];
            O[j][0] *= f0; O[j][1] *= f0;
            O[j][2] *= f1; O[j][3] *= f1;
        }
#pragma unroll
        for (int off = 1; off < 4; off <<= 1) {
            rs0 += __shfl_xor_sync(0xffffffffu, rs0, off);
            rs1 += __shfl_xor_sync(0xffffffffu, rs1, off);
        }
        l0 = l0 * f0 + rs0;
        l1 = l1 * f1 + rs1;

        // P fragments from S registers
        uint32_t ap[4][4];
#pragma unroll
        for (int ks = 0; ks < 4; ks++) {
            ap[ks][0] = packh2(s[2*ks][0],   s[2*ks][1]);
            ap[ks][1] = packh2(s[2*ks][2],   s[2*ks][3]);
            ap[ks][2] = packh2(s[2*ks+1][0], s[2*ks+1][1]);
            ap[ks][3] = packh2(s[2*ks+1][2], s[2*ks+1][3]);
        }

        // O += P @ V
#pragma unroll
        for (int ks = 0; ks < 4; ks++) {
#pragma unroll
            for (int p = 0; p < 4; p++) {
                uint32_t bv[4];
                ldsm_x4_t(vbase + ((ks*16 + lrow)*ASTR + p*16 + lcol8)*2,
                          bv[0], bv[1], bv[2], bv[3]);
                MMA16816(O[2*p],   ap[ks][0], ap[ks][1], ap[ks][2], ap[ks][3], bv[0], bv[1]);
                MMA16816(O[2*p+1], ap[ks][0], ap[ks][1], ap[ks][2], ap[ks][3], bv[2], bv[3]);
            }
        }
    }

    float inv0 = 1.0f / l0, inv1 = 1.0f / l1;
#pragma unroll
    for (int j = 0; j < 8; j++) {
        int col = h*HD + 8*j + 2*qid;
        *reinterpret_cast<uint32_t*>(&o[(size_t)(b*LL + qg0)*DD + col]) =
            packh2(O[j][0]*inv0, O[j][1]*inv0);
        *reinterpret_cast<uint32_t*>(&o[(size_t)(b*LL + qg1)*DD + col]) =
            packh2(O[j][2]*inv1, O[j][3]*inv1);
    }
}

// ---------------------------------------------------------------------------
// Block reduction + fused add+LN
// ---------------------------------------------------------------------------
__device__ __forceinline__ float block_sum256(float v, volatile float* red) {
#pragma unroll
    for (int o = 16; o; o >>= 1) v += __shfl_xor_sync(0xffffffffu, v, o);
    if ((threadIdx.x & 31) == 0) red[threadIdx.x >> 5] = v;
    __syncthreads();
    if (threadIdx.x == 0) {
        float s = red[0];
#pragma unroll
        for (int i = 1; i < 8; i++) s += red[i];
        red[0] = s;
    }
    __syncthreads();
    float r = red[0];
    __syncthreads();
    return r;
}

__global__ __launch_bounds__(256)
void add_ln_kernel(float* __restrict__ x, const float* __restrict__ r,
                   const float* __restrict__ w, const float* __restrict__ b,
                   __half* __restrict__ hx) {
    int row = blockIdx.x;
    int tid = threadIdx.x;
    __shared__ float buf[DD];
    __shared__ float red[8];

    float s = 0.f;
    for (int i = tid; i < DD; i += 256) {
        float v = x[(size_t)row*DD + i] + r[(size_t)row*DD + i];
        buf[i] = v;
        s += v;
    }
    __syncthreads();
    float mean = block_sum256(s, red) * (1.0f / DD);

    float vs = 0.f;
    for (int i = tid; i < DD; i += 256) {
        float d = buf[i] - mean;
        vs += d * d;
    }
    float var = block_sum256(vs, red) * (1.0f / DD);
    float inv = rsqrtf(var + 1e-5f);

    for (int i = tid; i < DD; i += 256) {
        float v = (buf[i] - mean) * inv * w[i] + b[i];
        x[(size_t)row*DD + i]  = v;
        hx[(size_t)row*DD + i] = __float2half(v);
    }
}

// ---------------------------------------------------------------------------
// Host launcher
// ---------------------------------------------------------------------------
static inline void conv(const float* s, __half* d, long n) {
    int blocks = (int)((n/4 + 255) / 256);
    f2h_kernel<<<blocks, 256>>>(s, d, (int)n);
}

extern "C" void kernel_launch(void* const* d_in, const int* in_sizes, int n_in,
                              void* d_out, int out_size) {
    const int*   ids   = (const int*)  d_in[0];
    const float* tok   = (const float*)d_in[1];
    const float* pos   = (const float*)d_in[2];
    const float* qkv_w = (const float*)d_in[3];
    const float* qkv_b = (const float*)d_in[4];
    const float* out_w = (const float*)d_in[5];
    const float* out_b = (const float*)d_in[6];
    const float* ln1_w = (const float*)d_in[7];
    const float* ln1_b = (const float*)d_in[8];
    const float* ln2_w = (const float*)d_in[9];
    const float* ln2_b = (const float*)d_in[10];
    const float* ff1_w = (const float*)d_in[11];
    const float* ff1_b = (const float*)d_in[12];
    const float* ff2_w = (const float*)d_in[13];
    const float* ff2_b = (const float*)d_in[14];
    float* out = (float*)d_out;

    float *x, *tmp;
    int *rel, *seg;
    __half *hqkv, *hx, *hatt, *hff, *htok, *hqkvw, *houtw, *hff1w, *hff2w;
    cudaGetSymbolAddress((void**)&x,    g_x);
    cudaGetSymbolAddress((void**)&tmp,  g_tmp);
    cudaGetSymbolAddress((void**)&rel,  g_rel);
    cudaGetSymbolAddress((void**)&seg,  g_seg);
    cudaGetSymbolAddress((void**)&hqkv, h_qkv);
    cudaGetSymbolAddress((void**)&hx,   h_x);
    cudaGetSymbolAddress((void**)&hatt, h_att);
    cudaGetSymbolAddress((void**)&hff,  h_ff);
    cudaGetSymbolAddress((void**)&htok, h_tok);
    cudaGetSymbolAddress((void**)&hqkvw, h_qkvw);
    cudaGetSymbolAddress((void**)&houtw, h_outw);
    cudaGetSymbolAddress((void**)&hff1w, h_ff1w);
    cudaGetSymbolAddress((void**)&hff2w, h_ff2w);

    // operand conversions (deterministic, every launch)
    conv(tok,   htok,  (long)VV*DD);
    conv(qkv_w, hqkvw, (long)NLAY*3*DD*DD);
    conv(out_w, houtw, (long)NLAY*DD*DD);
    conv(ff1_w, hff1w, (long)NLAY*DFFN*DD);
    conv(ff2_w, hff2w, (long)NLAY*DD*DFFN);

    meta_kernel<<<BB, 32>>>(ids, rel, seg);
    embed_kernel<<<ROWS, 256>>>(ids, rel, tok, pos, x, hx);

    const int MT = ROWS / 128;  // 16, fast axis

    for (int l = 0; l < NLAY; l++) {
        // qkv (fp16 out, feeds attention directly)
        gemm_h<false,true><<<dim3(MT, 3*DD/128), 256>>>(
            hx, hqkvw + (size_t)l*3*DD*DD, qkv_b + (size_t)l*3*DD, hqkv,
            ROWS, 3*DD, DD);

        attn_mma_kernel<<<dim3(LL/128, HH, BB), 256>>>(hqkv, seg, hatt);

        gemm_h<false,false><<<dim3(MT, DD/128), 256>>>(
            hatt, houtw + (size_t)l*DD*DD, out_b + (size_t)l*DD, tmp,
            ROWS, DD, DD);

        add_ln_kernel<<<ROWS, 256>>>(x, tmp, ln1_w + (size_t)l*DD, ln1_b + (size_t)l*DD, hx);

        gemm_h<true,true><<<dim3(MT, DFFN/128), 256>>>(
            hx, hff1w + (size_t)l*DFFN*DD, ff1_b + (size_t)l*DFFN, hff,
            ROWS, DFFN, DD);

        gemm_h<false,false><<<dim3(MT, DD/128), 256>>>(
            hff, hff2w + (size_t)l*DD*DFFN, ff2_b + (size_t)l*DD, tmp,
            ROWS, DD, DFFN);

        add_ln_kernel<<<ROWS, 256>>>(x, tmp, ln2_w + (size_t)l*DD, ln2_b + (size_t)l*DD, hx);
    }

    gemm_h<false,false><<<dim3(MT, (VV + 127)/128), 256>>>(
        hx, htok, nullptr, out, ROWS, VV, DD);
}